// round 5
// baseline (speedup 1.0000x reference)
#include <cuda_runtime.h>
#include <cstdint>
#include <cstddef>

#define N_NODES   50000
#define N_EDGES   800000
#define C_DIM     256
#define R_REL     4
#define NBUCKETS  (R_REL * N_NODES)          // 200000
#define SCAN_BS   1024
#define NSCANBLK  ((NBUCKETS + SCAN_BS - 1) / SCAN_BS)   // 196

// -------------------- scratch (small static device globals, ~4.8 MB) -----
__device__ int g_deg[NBUCKETS];
__device__ int g_off[NBUCKETS];
__device__ int g_cursor[NBUCKETS];
__device__ int g_eidx[N_EDGES];
__device__ int g_bsum[SCAN_BS];
__device__ int g_bsumx[SCAN_BS];

// Edge validity predicate — MUST be identical in hist and bucket.
__device__ __forceinline__ bool edge_ok(int s, int d, int r) {
    return ((unsigned)s < (unsigned)N_NODES) &&
           ((unsigned)d < (unsigned)N_NODES) &&
           ((unsigned)r < (unsigned)R_REL);
}

// ---------------------------------------------------------------------------
// CSR build over (relation, dst) buckets.  Edges read as INT32.
// ---------------------------------------------------------------------------
__global__ void zero_counts_kernel() {
    int i = blockIdx.x * blockDim.x + threadIdx.x;
    if (i < NBUCKETS) { g_deg[i] = 0; g_cursor[i] = 0; }
}

__global__ void hist_kernel(const int* __restrict__ edge_index,
                            const int* __restrict__ edge_type) {
    int e = blockIdx.x * blockDim.x + threadIdx.x;
    if (e >= N_EDGES) return;
    int s = edge_index[e];
    int d = edge_index[N_EDGES + e];
    int r = edge_type[e];
    if (!edge_ok(s, d, r)) return;
    atomicAdd(&g_deg[r * N_NODES + d], 1);
}

__global__ void scan_blocks_kernel() {
    __shared__ int sh[SCAN_BS];
    const int tid = threadIdx.x;
    const int gid = blockIdx.x * SCAN_BS + tid;
    int v = (gid < NBUCKETS) ? g_deg[gid] : 0;
    sh[tid] = v;
    __syncthreads();
    for (int o = 1; o < SCAN_BS; o <<= 1) {
        int t = (tid >= o) ? sh[tid - o] : 0;
        __syncthreads();
        sh[tid] += t;
        __syncthreads();
    }
    int incl = sh[tid];
    if (gid < NBUCKETS) g_off[gid] = incl - v;
    if (tid == SCAN_BS - 1) g_bsum[blockIdx.x] = incl;
}

__global__ void scan_top_kernel() {
    __shared__ int sh[256];
    const int tid = threadIdx.x;
    int v = (tid < NSCANBLK) ? g_bsum[tid] : 0;
    sh[tid] = v;
    __syncthreads();
    for (int o = 1; o < 256; o <<= 1) {
        int t = (tid >= o) ? sh[tid - o] : 0;
        __syncthreads();
        sh[tid] += t;
        __syncthreads();
    }
    g_bsumx[tid] = sh[tid] - v;   // exclusive
}

__global__ void scan_add_kernel() {
    int i = blockIdx.x * blockDim.x + threadIdx.x;
    if (i < NBUCKETS) g_off[i] += g_bsumx[i >> 10];
}

__global__ void bucket_kernel(const int* __restrict__ edge_index,
                              const int* __restrict__ edge_type) {
    int e = blockIdx.x * blockDim.x + threadIdx.x;
    if (e >= N_EDGES) return;
    int s = edge_index[e];
    int d = edge_index[N_EDGES + e];
    int r = edge_type[e];
    if (!edge_ok(s, d, r)) return;
    int b = r * N_NODES + d;
    int pos = g_off[b] + atomicAdd(&g_cursor[b], 1);
    if ((unsigned)pos < (unsigned)N_EDGES)   // belt-and-braces: never trap
        g_eidx[pos] = s;
}

// ---------------------------------------------------------------------------
// Fused: per-block in-smem aggregation + 5-way GEMM + bias + attention gate.
//  u0[n] = X[n]@Wroot + bias + sum_r mean_{e:(r,dst=n)} X[src_e] @ W_r
//  a = sigmoid([u0,x].attW + attB);  h = tanh(u0)*a + x*(1-a)
// Tile: 64 nodes x 256 outs, 256 threads.
// Dynamic smem: At[256][65] (A tile, transposed, padded) + Ws[16][64] float4.
// ---------------------------------------------------------------------------
#define NB    64
#define KB    16
#define S_AT  65
#define AT_FLOATS (C_DIM * S_AT)          // 16640 floats
#define WS_F4     (KB * (C_DIM / 4))      // 1024 float4
#define SMEM_BYTES ((AT_FLOATS + WS_F4 * 4) * 4)   // 82,944 bytes

__device__ __forceinline__ void fma4(float4& acc, float a, const float4& w) {
    acc.x = fmaf(a, w.x, acc.x);
    acc.y = fmaf(a, w.y, acc.y);
    acc.z = fmaf(a, w.z, acc.z);
    acc.w = fmaf(a, w.w, acc.w);
}

__global__ void __launch_bounds__(256, 2) fused_gemm_gate(
    const float* __restrict__ X,      // [N, C]
    const float* __restrict__ relW,   // [R, C, C]
    const float* __restrict__ rootW,  // [C, C]
    const float* __restrict__ bias,   // [C]
    const float* __restrict__ attW,   // [2C]
    const float* __restrict__ attB,   // [1]
    float* __restrict__ out)          // [N, C]
{
    extern __shared__ float smem[];
    float*  At  = smem;                                        // [256][S_AT]
    float4* Ws4 = reinterpret_cast<float4*>(smem + AT_FLOATS); // [16][64]

    const int t    = threadIdx.x;
    const int lane = t & 31;
    const int warp = t >> 5;            // 0..7
    const int ow   = t & 15;
    const int ng   = t >> 4;            // 0..15
    const int node0 = blockIdx.x * NB;

    const int w_kk  = t >> 4;           // 0..15 (k row for W staging)
    const int w_seg = t & 15;           // 0..15

    float4 acc[4][4];
    #pragma unroll
    for (int i = 0; i < 4; i++)
        #pragma unroll
        for (int j = 0; j < 4; j++) acc[i][j] = make_float4(0.f, 0.f, 0.f, 0.f);

    float4 wReg[4];

    for (int m = 0; m < 5; ++m) {
        const float* Wm = (m == 0) ? rootW : (relW + (size_t)(m - 1) * C_DIM * C_DIM);

        // prefetch W chunk 0 of this matrix (overlaps the At fill below)
        #pragma unroll
        for (int j = 0; j < 4; j++)
            wReg[j] = *reinterpret_cast<const float4*>(
                Wm + (size_t)w_kk * C_DIM + 4 * (w_seg + 16 * j));

        // ---- fill At (transposed A tile) ----
        if (m == 0) {
            // copy X rows
            #pragma unroll
            for (int it = 0; it < 16; ++it) {
                const int f4 = it * 256 + t;     // 0..4095
                const int nb = f4 >> 6;          // node within tile
                const int kq = f4 & 63;          // float4 index within row
                float4 v = make_float4(0.f, 0.f, 0.f, 0.f);
                const int node = node0 + nb;
                if (node < N_NODES)
                    v = *reinterpret_cast<const float4*>(X + (size_t)node * C_DIM + 4 * kq);
                At[(4 * kq + 0) * S_AT + nb] = v.x;
                At[(4 * kq + 1) * S_AT + nb] = v.y;
                At[(4 * kq + 2) * S_AT + nb] = v.z;
                At[(4 * kq + 3) * S_AT + nb] = v.w;
            }
        } else {
            // gather-mean for relation m-1: one warp per bucket, 8 buckets/warp
            const int r = m - 1;
            for (int nb = warp; nb < NB; nb += 8) {
                const int node = node0 + nb;
                float4 s0 = make_float4(0.f, 0.f, 0.f, 0.f);
                float4 s1 = make_float4(0.f, 0.f, 0.f, 0.f);
                int deg = 0;
                if (node < N_NODES) {
                    const int b = r * N_NODES + node;
                    deg = g_deg[b];
                    const int start = g_off[b];
                    for (int e = 0; e < deg; ++e) {
                        const int src = g_eidx[start + e];
                        const float4* xr = reinterpret_cast<const float4*>(X + (size_t)src * C_DIM);
                        const float4 v0 = xr[2 * lane];
                        const float4 v1 = xr[2 * lane + 1];
                        s0.x += v0.x; s0.y += v0.y; s0.z += v0.z; s0.w += v0.w;
                        s1.x += v1.x; s1.y += v1.y; s1.z += v1.z; s1.w += v1.w;
                    }
                }
                const float inv = (deg > 0) ? (1.0f / (float)deg) : 0.0f;
                const int k0 = lane * 8;
                At[(k0 + 0) * S_AT + nb] = s0.x * inv;
                At[(k0 + 1) * S_AT + nb] = s0.y * inv;
                At[(k0 + 2) * S_AT + nb] = s0.z * inv;
                At[(k0 + 3) * S_AT + nb] = s0.w * inv;
                At[(k0 + 4) * S_AT + nb] = s1.x * inv;
                At[(k0 + 5) * S_AT + nb] = s1.y * inv;
                At[(k0 + 6) * S_AT + nb] = s1.z * inv;
                At[(k0 + 7) * S_AT + nb] = s1.w * inv;
            }
        }
        __syncthreads();   // At ready; previous matrix's Ws consumers done

        // ---- 16 k-chunks of GEMM ----
        for (int c = 0; c < KB; ++c) {
            // stage prefetched W chunk into smem
            #pragma unroll
            for (int j = 0; j < 4; j++)
                Ws4[w_kk * 64 + w_seg + 16 * j] = wReg[j];
            __syncthreads();

            // prefetch next chunk of this matrix
            if (c < KB - 1) {
                #pragma unroll
                for (int j = 0; j < 4; j++)
                    wReg[j] = *reinterpret_cast<const float4*>(
                        Wm + (size_t)((c + 1) * KB + w_kk) * C_DIM + 4 * (w_seg + 16 * j));
            }

            // compute 16 k-steps
            #pragma unroll
            for (int kk = 0; kk < KB; ++kk) {
                const int k = c * KB + kk;
                float av[4];
                #pragma unroll
                for (int i = 0; i < 4; ++i) av[i] = At[k * S_AT + (ng << 2) + i];
                float4 wv[4];
                #pragma unroll
                for (int j = 0; j < 4; ++j) wv[j] = Ws4[kk * 64 + ow + 16 * j];
                #pragma unroll
                for (int i = 0; i < 4; ++i)
                    #pragma unroll
                    for (int j = 0; j < 4; ++j)
                        fma4(acc[i][j], av[i], wv[j]);
            }
            __syncthreads();   // done with Ws before next store (and At before refill)
        }
    }

    // ---------------- epilogue: bias + attention gate ----------------
    const float attB0 = attB[0];

    float4 bv[4], awU[4], awX[4];
    #pragma unroll
    for (int j = 0; j < 4; ++j) {
        const int c0 = 4 * (ow + 16 * j);
        bv[j]  = *reinterpret_cast<const float4*>(bias + c0);
        awU[j] = *reinterpret_cast<const float4*>(attW + c0);
        awX[j] = *reinterpret_cast<const float4*>(attW + C_DIM + c0);
    }

    #pragma unroll
    for (int i = 0; i < 4; ++i) {
        const int node_g = node0 + (ng << 2) + i;
        const bool valid = node_g < N_NODES;
        const float4* xrow = reinterpret_cast<const float4*>(X + (size_t)node_g * C_DIM);

        float4 xv[4];
        float pz = 0.f;
        #pragma unroll
        for (int j = 0; j < 4; ++j) {
            float4 u = acc[i][j];
            u.x += bv[j].x; u.y += bv[j].y; u.z += bv[j].z; u.w += bv[j].w;
            acc[i][j] = u;

            float4 x4 = make_float4(0.f, 0.f, 0.f, 0.f);
            if (valid) x4 = xrow[ow + 16 * j];
            xv[j] = x4;

            pz += u.x * awU[j].x + u.y * awU[j].y + u.z * awU[j].z + u.w * awU[j].w;
            pz += x4.x * awX[j].x + x4.y * awX[j].y + x4.z * awX[j].z + x4.w * awX[j].w;
        }

        // reduce across the 16 lanes of this node group (xor masks < 16 keep
        // the two 16-lane halves independent)
        float z = pz;
        z += __shfl_xor_sync(0xffffffffu, z, 1);
        z += __shfl_xor_sync(0xffffffffu, z, 2);
        z += __shfl_xor_sync(0xffffffffu, z, 4);
        z += __shfl_xor_sync(0xffffffffu, z, 8);

        const float a = 1.0f / (1.0f + expf(-(z + attB0)));
        const float one_m_a = 1.0f - a;

        if (valid) {
            float4* orow = reinterpret_cast<float4*>(out + (size_t)node_g * C_DIM);
            #pragma unroll
            for (int j = 0; j < 4; ++j) {
                const float4 u = acc[i][j];
                float4 h;
                h.x = tanhf(u.x) * a + xv[j].x * one_m_a;
                h.y = tanhf(u.y) * a + xv[j].y * one_m_a;
                h.z = tanhf(u.z) * a + xv[j].z * one_m_a;
                h.w = tanhf(u.w) * a + xv[j].w * one_m_a;
                orow[ow + 16 * j] = h;
            }
        }
    }
}

// ---------------------------------------------------------------------------
// Launch
// ---------------------------------------------------------------------------
extern "C" void kernel_launch(void* const* d_in, const int* in_sizes, int n_in,
                              void* d_out, int out_size) {
    const float* X     = (const float*)d_in[0];
    const int*   ei    = (const int*)d_in[1];     // int32 (JAX x64 disabled)
    const int*   et    = (const int*)d_in[2];     // int32
    const float* relW  = (const float*)d_in[3];
    const float* rootW = (const float*)d_in[4];
    const float* bias  = (const float*)d_in[5];
    const float* attW  = (const float*)d_in[6];
    const float* attB  = (const float*)d_in[7];
    float*       out   = (float*)d_out;
    (void)in_sizes; (void)n_in; (void)out_size;

    cudaFuncSetAttribute(fused_gemm_gate,
                         cudaFuncAttributeMaxDynamicSharedMemorySize, SMEM_BYTES);

    zero_counts_kernel<<<(NBUCKETS + 255) / 256, 256>>>();
    hist_kernel<<<(N_EDGES + 255) / 256, 256>>>(ei, et);
    scan_blocks_kernel<<<NSCANBLK, SCAN_BS>>>();
    scan_top_kernel<<<1, 256>>>();
    scan_add_kernel<<<(NBUCKETS + 255) / 256, 256>>>();
    bucket_kernel<<<(N_EDGES + 255) / 256, 256>>>(ei, et);
    fused_gemm_gate<<<(N_NODES + NB - 1) / NB, 256, SMEM_BYTES>>>(
        X, relW, rootW, bias, attW, attB, out);
}

// round 6
// speedup vs baseline: 1.5595x; 1.5595x over previous
#include <cuda_runtime.h>
#include <cuda_bf16.h>
#include <cstdint>
#include <cstddef>

#define N_NODES   50000
#define N_EDGES   800000
#define C_DIM     256
#define R_REL     4
#define NBUCKETS  (R_REL * N_NODES)
#define SCAN_BS   1024
#define NSCANBLK  ((NBUCKETS + SCAN_BS - 1) / SCAN_BS)

// -------------------- scratch --------------------
__device__ int g_deg[NBUCKETS];
__device__ int g_off[NBUCKETS];
__device__ int g_cursor[NBUCKETS];
__device__ int g_eidx[N_EDGES];
__device__ int g_bsum[SCAN_BS];
__device__ int g_bsumx[SCAN_BS];
// pre-split weights, concat [root, rel0..3] -> [5][256][256] bf16 hi/lo
__device__ __nv_bfloat16 g_Wh[5 * C_DIM * C_DIM];
__device__ __nv_bfloat16 g_Wl[5 * C_DIM * C_DIM];

__device__ __forceinline__ bool edge_ok(int s, int d, int r) {
    return ((unsigned)s < (unsigned)N_NODES) &&
           ((unsigned)d < (unsigned)N_NODES) &&
           ((unsigned)r < (unsigned)R_REL);
}

// ---------------------------------------------------------------------------
// CSR build (edges are INT32)
// ---------------------------------------------------------------------------
__global__ void zero_counts_kernel() {
    int i = blockIdx.x * blockDim.x + threadIdx.x;
    if (i < NBUCKETS) { g_deg[i] = 0; g_cursor[i] = 0; }
}

__global__ void hist_kernel(const int* __restrict__ edge_index,
                            const int* __restrict__ edge_type) {
    int e = blockIdx.x * blockDim.x + threadIdx.x;
    if (e >= N_EDGES) return;
    int s = edge_index[e];
    int d = edge_index[N_EDGES + e];
    int r = edge_type[e];
    if (!edge_ok(s, d, r)) return;
    atomicAdd(&g_deg[r * N_NODES + d], 1);
}

__global__ void scan_blocks_kernel() {
    __shared__ int sh[SCAN_BS];
    const int tid = threadIdx.x;
    const int gid = blockIdx.x * SCAN_BS + tid;
    int v = (gid < NBUCKETS) ? g_deg[gid] : 0;
    sh[tid] = v;
    __syncthreads();
    for (int o = 1; o < SCAN_BS; o <<= 1) {
        int t = (tid >= o) ? sh[tid - o] : 0;
        __syncthreads();
        sh[tid] += t;
        __syncthreads();
    }
    int incl = sh[tid];
    if (gid < NBUCKETS) g_off[gid] = incl - v;
    if (tid == SCAN_BS - 1) g_bsum[blockIdx.x] = incl;
}

__global__ void scan_top_kernel() {
    __shared__ int sh[256];
    const int tid = threadIdx.x;
    int v = (tid < NSCANBLK) ? g_bsum[tid] : 0;
    sh[tid] = v;
    __syncthreads();
    for (int o = 1; o < 256; o <<= 1) {
        int t = (tid >= o) ? sh[tid - o] : 0;
        __syncthreads();
        sh[tid] += t;
        __syncthreads();
    }
    g_bsumx[tid] = sh[tid] - v;
}

__global__ void scan_add_kernel() {
    int i = blockIdx.x * blockDim.x + threadIdx.x;
    if (i < NBUCKETS) g_off[i] += g_bsumx[i >> 10];
}

__global__ void bucket_kernel(const int* __restrict__ edge_index,
                              const int* __restrict__ edge_type) {
    int e = blockIdx.x * blockDim.x + threadIdx.x;
    if (e >= N_EDGES) return;
    int s = edge_index[e];
    int d = edge_index[N_EDGES + e];
    int r = edge_type[e];
    if (!edge_ok(s, d, r)) return;
    int b = r * N_NODES + d;
    int pos = g_off[b] + atomicAdd(&g_cursor[b], 1);
    if ((unsigned)pos < (unsigned)N_EDGES)
        g_eidx[pos] = s;
}

// ---------------------------------------------------------------------------
// Weight pre-split: fp32 -> bf16 hi + bf16 lo residual
// ---------------------------------------------------------------------------
__global__ void wsplit_kernel(const float* __restrict__ relW,
                              const float* __restrict__ rootW) {
    int i = blockIdx.x * blockDim.x + threadIdx.x;
    if (i >= 5 * C_DIM * C_DIM) return;
    int m = i / (C_DIM * C_DIM);
    int o = i % (C_DIM * C_DIM);
    float v = (m == 0) ? rootW[o] : relW[(size_t)(m - 1) * C_DIM * C_DIM + o];
    __nv_bfloat16 h = __float2bfloat16(v);
    g_Wh[i] = h;
    g_Wl[i] = __float2bfloat16(v - __bfloat162float(h));
}

// ---------------------------------------------------------------------------
// Fused MMA kernel: in-smem gather-mean + split-bf16 5-way GEMM + gate
// Block: 256 threads (8 warps as 4m x 2n), tile 64 nodes x 256 outs.
// ---------------------------------------------------------------------------
#define NB   64
#define SA   264   // half-stride of A/W smem rows (conflict-free for ldmatrix)
#define SU   260   // float-stride of u0 smem
#define KCH  32    // k per W chunk
#define NCH  (C_DIM / KCH)  // 8

#define A_BYTES   (2 * NB * SA * 2)            // Ah+Al: 67584
#define W_BYTES   (2 * KCH * SA * 2)           // one of Wh/Wl (2 bufs): 33792
#define SMEM_BYTES (A_BYTES + 2 * W_BYTES)     // 135168

__device__ __forceinline__ void cp16(void* dst_smem, const void* src) {
    unsigned int d = (unsigned int)__cvta_generic_to_shared(dst_smem);
    asm volatile("cp.async.cg.shared.global [%0], [%1], 16;" :: "r"(d), "l"(src));
}

__device__ __forceinline__ void ldsm4(const void* p, unsigned& r0, unsigned& r1,
                                      unsigned& r2, unsigned& r3) {
    unsigned a = (unsigned)__cvta_generic_to_shared(p);
    asm volatile("ldmatrix.sync.aligned.m8n8.x4.shared.b16 {%0,%1,%2,%3}, [%4];"
                 : "=r"(r0), "=r"(r1), "=r"(r2), "=r"(r3) : "r"(a));
}

__device__ __forceinline__ void ldsm4t(const void* p, unsigned& r0, unsigned& r1,
                                       unsigned& r2, unsigned& r3) {
    unsigned a = (unsigned)__cvta_generic_to_shared(p);
    asm volatile("ldmatrix.sync.aligned.m8n8.x4.trans.shared.b16 {%0,%1,%2,%3}, [%4];"
                 : "=r"(r0), "=r"(r1), "=r"(r2), "=r"(r3) : "r"(a));
}

__device__ __forceinline__ void mma16816(float* c, unsigned a0, unsigned a1,
                                         unsigned a2, unsigned a3,
                                         unsigned b0, unsigned b1) {
    asm volatile(
        "mma.sync.aligned.m16n8k16.row.col.f32.bf16.bf16.f32 "
        "{%0,%1,%2,%3}, {%4,%5,%6,%7}, {%8,%9}, {%0,%1,%2,%3};"
        : "+f"(c[0]), "+f"(c[1]), "+f"(c[2]), "+f"(c[3])
        : "r"(a0), "r"(a1), "r"(a2), "r"(a3), "r"(b0), "r"(b1));
}

__device__ __forceinline__ void split_store(__nv_bfloat16* hp, __nv_bfloat16* lp, float v) {
    __nv_bfloat16 h = __float2bfloat16(v);
    *hp = h;
    *lp = __float2bfloat16(v - __bfloat162float(h));
}

__global__ void __launch_bounds__(256, 1) fused_mma_gate(
    const float* __restrict__ X,
    const float* __restrict__ bias,
    const float* __restrict__ attW,
    const float* __restrict__ attB,
    float* __restrict__ out)
{
    extern __shared__ char smem[];
    __nv_bfloat16* Ah  = (__nv_bfloat16*)smem;
    __nv_bfloat16* Al  = Ah + NB * SA;
    __nv_bfloat16* WhS = (__nv_bfloat16*)(smem + A_BYTES);
    __nv_bfloat16* WlS = (__nv_bfloat16*)(smem + A_BYTES + W_BYTES);
    float*         u0s = (float*)smem;   // overlays Ah/Al after GEMM

    const int t    = threadIdx.x;
    const int lane = t & 31;
    const int warp = t >> 5;
    const int wm   = warp & 3;      // m block (16 rows each)
    const int wn   = warp >> 2;     // n block (128 cols each)
    const int node0 = blockIdx.x * NB;

    float acc[16][4];
    #pragma unroll
    for (int i = 0; i < 16; ++i)
        #pragma unroll
        for (int j = 0; j < 4; ++j) acc[i][j] = 0.f;

    // W chunk loader: 32 k-rows x 256 cols, hi+lo, via cp.async 16B
    auto load_w_chunk = [&](int m, int c, int buf) {
        const size_t gbase = ((size_t)m * C_DIM + c * KCH) * C_DIM;
        #pragma unroll
        for (int i = 0; i < 4; ++i) {
            int p   = t + 256 * i;          // 0..1023
            int row = p >> 5, seg = p & 31;
            size_t g = gbase + (size_t)row * C_DIM + seg * 8;
            int sm   = buf * KCH * SA + row * SA + seg * 8;
            cp16(WhS + sm, g_Wh + g);
            cp16(WlS + sm, g_Wl + g);
        }
        asm volatile("cp.async.commit_group;");
    };

    int buf = 0;
    load_w_chunk(0, 0, 0);     // prefetch first chunk

    for (int m = 0; m < 5; ++m) {
        // ---- build A tile (split bf16 hi/lo) ----
        if (m == 0) {
            #pragma unroll
            for (int it = 0; it < 16; ++it) {
                const int f4 = it * 256 + t;
                const int nb = f4 >> 6;
                const int kq = f4 & 63;
                float4 v = make_float4(0.f, 0.f, 0.f, 0.f);
                const int node = node0 + nb;
                if (node < N_NODES)
                    v = *reinterpret_cast<const float4*>(X + (size_t)node * C_DIM + 4 * kq);
                const int o = nb * SA + 4 * kq;
                split_store(Ah + o + 0, Al + o + 0, v.x);
                split_store(Ah + o + 1, Al + o + 1, v.y);
                split_store(Ah + o + 2, Al + o + 2, v.z);
                split_store(Ah + o + 3, Al + o + 3, v.w);
            }
        } else {
            const int r = m - 1;
            for (int nb = warp; nb < NB; nb += 8) {
                const int node = node0 + nb;
                float s0[4] = {0.f, 0.f, 0.f, 0.f};
                float s1[4] = {0.f, 0.f, 0.f, 0.f};
                int deg = 0;
                if (node < N_NODES) {
                    const int b = r * N_NODES + node;
                    deg = g_deg[b];
                    const int start = g_off[b];
                    for (int e = 0; e < deg; ++e) {
                        const int src = g_eidx[start + e];
                        const float4* xr = reinterpret_cast<const float4*>(X + (size_t)src * C_DIM);
                        const float4 v0 = xr[2 * lane];
                        const float4 v1 = xr[2 * lane + 1];
                        s0[0] += v0.x; s0[1] += v0.y; s0[2] += v0.z; s0[3] += v0.w;
                        s1[0] += v1.x; s1[1] += v1.y; s1[2] += v1.z; s1[3] += v1.w;
                    }
                }
                const float inv = (deg > 0) ? (1.0f / (float)deg) : 0.0f;
                const int o = nb * SA + 8 * lane;
                #pragma unroll
                for (int q = 0; q < 4; ++q)
                    split_store(Ah + o + q, Al + o + q, s0[q] * inv);
                #pragma unroll
                for (int q = 0; q < 4; ++q)
                    split_store(Ah + o + 4 + q, Al + o + 4 + q, s1[q] * inv);
            }
        }
        __syncthreads();   // A ready (prev matrix's consumers already synced)

        // ---- 8 chunks of k=32 ----
        for (int c = 0; c < NCH; ++c) {
            const bool has_next = !(m == 4 && c == NCH - 1);
            if (has_next) {
                const int mn = (c == NCH - 1) ? m + 1 : m;
                const int cn = (c == NCH - 1) ? 0 : c + 1;
                load_w_chunk(mn, cn, buf ^ 1);
                asm volatile("cp.async.wait_group 1;");
            } else {
                asm volatile("cp.async.wait_group 0;");
            }
            __syncthreads();   // current W buf visible

            const __nv_bfloat16* Wh_ = WhS + buf * KCH * SA;
            const __nv_bfloat16* Wl_ = WlS + buf * KCH * SA;

            #pragma unroll
            for (int s = 0; s < 2; ++s) {
                const int k0 = c * KCH + s * 16;
                const __nv_bfloat16* ap =
                    Ah + (wm * 16 + (lane & 15)) * SA + k0 + (lane >> 4) * 8;
                unsigned ah0, ah1, ah2, ah3, al0, al1, al2, al3;
                ldsm4(ap, ah0, ah1, ah2, ah3);
                ldsm4(ap + NB * SA, al0, al1, al2, al3);   // Al same offset

                const int krow = s * 16 + (lane & 15);
                #pragma unroll
                for (int nt2 = 0; nt2 < 8; ++nt2) {
                    const int ncol = wn * 128 + nt2 * 16 + (lane >> 4) * 8;
                    unsigned bh0, bh1, bh2, bh3, bl0, bl1, bl2, bl3;
                    ldsm4t(Wh_ + krow * SA + ncol, bh0, bh1, bh2, bh3);
                    ldsm4t(Wl_ + krow * SA + ncol, bl0, bl1, bl2, bl3);
                    float* c0 = acc[2 * nt2];
                    float* c1 = acc[2 * nt2 + 1];
                    mma16816(c0, ah0, ah1, ah2, ah3, bh0, bh1);
                    mma16816(c1, ah0, ah1, ah2, ah3, bh2, bh3);
                    mma16816(c0, al0, al1, al2, al3, bh0, bh1);
                    mma16816(c1, al0, al1, al2, al3, bh2, bh3);
                    mma16816(c0, ah0, ah1, ah2, ah3, bl0, bl1);
                    mma16816(c1, ah0, ah1, ah2, ah3, bl2, bl3);
                }
            }
            __syncthreads();   // done reading buf & Ah before they're rewritten
            buf ^= 1;
        }
    }

    // ---- dump accumulators to smem (overlaying Ah/Al) ----
    #pragma unroll
    for (int nt = 0; nt < 16; ++nt) {
        const int row = wm * 16 + (lane >> 2);
        const int col = wn * 128 + nt * 8 + 2 * (lane & 3);
        u0s[row * SU + col]           = acc[nt][0];
        u0s[row * SU + col + 1]       = acc[nt][1];
        u0s[(row + 8) * SU + col]     = acc[nt][2];
        u0s[(row + 8) * SU + col + 1] = acc[nt][3];
    }
    __syncthreads();

    // ---------------- epilogue: bias + attention gate ----------------
    const int ow = t & 15;
    const int ng = t >> 4;
    const float attB0 = attB[0];

    float4 bv[4], awU[4], awX[4];
    #pragma unroll
    for (int j = 0; j < 4; ++j) {
        const int c0 = 4 * (ow + 16 * j);
        bv[j]  = *reinterpret_cast<const float4*>(bias + c0);
        awU[j] = *reinterpret_cast<const float4*>(attW + c0);
        awX[j] = *reinterpret_cast<const float4*>(attW + C_DIM + c0);
    }

    #pragma unroll
    for (int i = 0; i < 4; ++i) {
        const int node_l = (ng << 2) + i;
        const int node_g = node0 + node_l;
        const bool valid = node_g < N_NODES;
        const float4* xrow = reinterpret_cast<const float4*>(X + (size_t)node_g * C_DIM);

        float4 uu[4], xv[4];
        float pz = 0.f;
        #pragma unroll
        for (int j = 0; j < 4; ++j) {
            float4 u = *reinterpret_cast<const float4*>(u0s + node_l * SU + 4 * (ow + 16 * j));
            u.x += bv[j].x; u.y += bv[j].y; u.z += bv[j].z; u.w += bv[j].w;
            uu[j] = u;

            float4 x4 = make_float4(0.f, 0.f, 0.f, 0.f);
            if (valid) x4 = xrow[ow + 16 * j];
            xv[j] = x4;

            pz += u.x * awU[j].x + u.y * awU[j].y + u.z * awU[j].z + u.w * awU[j].w;
            pz += x4.x * awX[j].x + x4.y * awX[j].y + x4.z * awX[j].z + x4.w * awX[j].w;
        }

        float z = pz;
        z += __shfl_xor_sync(0xffffffffu, z, 1);
        z += __shfl_xor_sync(0xffffffffu, z, 2);
        z += __shfl_xor_sync(0xffffffffu, z, 4);
        z += __shfl_xor_sync(0xffffffffu, z, 8);

        const float a = 1.0f / (1.0f + expf(-(z + attB0)));
        const float one_m_a = 1.0f - a;

        if (valid) {
            float4* orow = reinterpret_cast<float4*>(out + (size_t)node_g * C_DIM);
            #pragma unroll
            for (int j = 0; j < 4; ++j) {
                const float4 u = uu[j];
                float4 h;
                h.x = tanhf(u.x) * a + xv[j].x * one_m_a;
                h.y = tanhf(u.y) * a + xv[j].y * one_m_a;
                h.z = tanhf(u.z) * a + xv[j].z * one_m_a;
                h.w = tanhf(u.w) * a + xv[j].w * one_m_a;
                orow[ow + 16 * j] = h;
            }
        }
    }
}

// ---------------------------------------------------------------------------
// Launch
// ---------------------------------------------------------------------------
extern "C" void kernel_launch(void* const* d_in, const int* in_sizes, int n_in,
                              void* d_out, int out_size) {
    const float* X     = (const float*)d_in[0];
    const int*   ei    = (const int*)d_in[1];     // int32
    const int*   et    = (const int*)d_in[2];     // int32
    const float* relW  = (const float*)d_in[3];
    const float* rootW = (const float*)d_in[4];
    const float* bias  = (const float*)d_in[5];
    const float* attW  = (const float*)d_in[6];
    const float* attB  = (const float*)d_in[7];
    float*       out   = (float*)d_out;
    (void)in_sizes; (void)n_in; (void)out_size;

    cudaFuncSetAttribute(fused_mma_gate,
                         cudaFuncAttributeMaxDynamicSharedMemorySize, SMEM_BYTES);

    zero_counts_kernel<<<(NBUCKETS + 255) / 256, 256>>>();
    hist_kernel<<<(N_EDGES + 255) / 256, 256>>>(ei, et);
    wsplit_kernel<<<(5 * C_DIM * C_DIM + 255) / 256, 256>>>(relW, rootW);
    scan_blocks_kernel<<<NSCANBLK, SCAN_BS>>>();
    scan_top_kernel<<<1, 256>>>();
    scan_add_kernel<<<(NBUCKETS + 255) / 256, 256>>>();
    bucket_kernel<<<(N_EDGES + 255) / 256, 256>>>(ei, et);
    fused_mma_gate<<<(N_NODES + NB - 1) / NB, 256, SMEM_BYTES>>>(
        X, bias, attW, attB, out);
}

// round 7
// speedup vs baseline: 1.8814x; 1.2064x over previous
#include <cuda_runtime.h>
#include <cuda_bf16.h>
#include <cstdint>
#include <cstddef>

#define N_NODES   50000
#define N_EDGES   800000
#define C_DIM     256
#define R_REL     4
#define NBUCKETS  (R_REL * N_NODES)
#define SCAN_BS   1024
#define NSCANBLK  ((NBUCKETS + SCAN_BS - 1) / SCAN_BS)

// -------------------- scratch --------------------
__device__ int g_deg[NBUCKETS];
__device__ int g_off[NBUCKETS];
__device__ int g_cursor[NBUCKETS];
__device__ int g_eidx[N_EDGES];
__device__ int g_bsum[SCAN_BS];
__device__ int g_bsumx[SCAN_BS];
// split weights [5][256][256] (root, rel0..3)
__device__ __nv_bfloat16 g_Wh[5 * C_DIM * C_DIM];
__device__ __nv_bfloat16 g_Wl[5 * C_DIM * C_DIM];
// split A operand [5][N][256]: m=0 -> X, m=1..4 -> per-relation means
__device__ __nv_bfloat16 g_Ah[(size_t)5 * N_NODES * C_DIM];
__device__ __nv_bfloat16 g_Al[(size_t)5 * N_NODES * C_DIM];

__device__ __forceinline__ bool edge_ok(int s, int d, int r) {
    return ((unsigned)s < (unsigned)N_NODES) &&
           ((unsigned)d < (unsigned)N_NODES) &&
           ((unsigned)r < (unsigned)R_REL);
}

// ---------------------------------------------------------------------------
// CSR build (edges are INT32)
// ---------------------------------------------------------------------------
__global__ void zero_counts_kernel() {
    int i = blockIdx.x * blockDim.x + threadIdx.x;
    if (i < NBUCKETS) { g_deg[i] = 0; g_cursor[i] = 0; }
}

__global__ void hist_kernel(const int* __restrict__ edge_index,
                            const int* __restrict__ edge_type) {
    int e = blockIdx.x * blockDim.x + threadIdx.x;
    if (e >= N_EDGES) return;
    int s = edge_index[e];
    int d = edge_index[N_EDGES + e];
    int r = edge_type[e];
    if (!edge_ok(s, d, r)) return;
    atomicAdd(&g_deg[r * N_NODES + d], 1);
}

__global__ void scan_blocks_kernel() {
    __shared__ int sh[SCAN_BS];
    const int tid = threadIdx.x;
    const int gid = blockIdx.x * SCAN_BS + tid;
    int v = (gid < NBUCKETS) ? g_deg[gid] : 0;
    sh[tid] = v;
    __syncthreads();
    for (int o = 1; o < SCAN_BS; o <<= 1) {
        int t = (tid >= o) ? sh[tid - o] : 0;
        __syncthreads();
        sh[tid] += t;
        __syncthreads();
    }
    int incl = sh[tid];
    if (gid < NBUCKETS) g_off[gid] = incl - v;
    if (tid == SCAN_BS - 1) g_bsum[blockIdx.x] = incl;
}

__global__ void scan_top_kernel() {
    __shared__ int sh[256];
    const int tid = threadIdx.x;
    int v = (tid < NSCANBLK) ? g_bsum[tid] : 0;
    sh[tid] = v;
    __syncthreads();
    for (int o = 1; o < 256; o <<= 1) {
        int t = (tid >= o) ? sh[tid - o] : 0;
        __syncthreads();
        sh[tid] += t;
        __syncthreads();
    }
    g_bsumx[tid] = sh[tid] - v;
}

__global__ void scan_add_kernel() {
    int i = blockIdx.x * blockDim.x + threadIdx.x;
    if (i < NBUCKETS) g_off[i] += g_bsumx[i >> 10];
}

__global__ void bucket_kernel(const int* __restrict__ edge_index,
                              const int* __restrict__ edge_type) {
    int e = blockIdx.x * blockDim.x + threadIdx.x;
    if (e >= N_EDGES) return;
    int s = edge_index[e];
    int d = edge_index[N_EDGES + e];
    int r = edge_type[e];
    if (!edge_ok(s, d, r)) return;
    int b = r * N_NODES + d;
    int pos = g_off[b] + atomicAdd(&g_cursor[b], 1);
    if ((unsigned)pos < (unsigned)N_EDGES)
        g_eidx[pos] = s;
}

// ---------------------------------------------------------------------------
// Split helpers
// ---------------------------------------------------------------------------
__device__ __forceinline__ void split1(float v, __nv_bfloat16& h, __nv_bfloat16& l) {
    h = __float2bfloat16(v);
    l = __float2bfloat16(v - __bfloat162float(h));
}

__global__ void wsplit_kernel(const float* __restrict__ relW,
                              const float* __restrict__ rootW) {
    int i = blockIdx.x * blockDim.x + threadIdx.x;
    if (i >= 5 * C_DIM * C_DIM) return;
    int m = i / (C_DIM * C_DIM);
    int o = i % (C_DIM * C_DIM);
    float v = (m == 0) ? rootW[o] : relW[(size_t)(m - 1) * C_DIM * C_DIM + o];
    split1(v, g_Wh[i], g_Wl[i]);
}

// X -> g_Ah[0]/g_Al[0]
__global__ void xsplit_kernel(const float* __restrict__ X) {
    size_t i = (size_t)blockIdx.x * blockDim.x + threadIdx.x;   // float4 index
    if (i >= (size_t)N_NODES * C_DIM / 4) return;
    float4 v = reinterpret_cast<const float4*>(X)[i];
    __nv_bfloat16 h[4], l[4];
    split1(v.x, h[0], l[0]); split1(v.y, h[1], l[1]);
    split1(v.z, h[2], l[2]); split1(v.w, h[3], l[3]);
    *reinterpret_cast<uint2*>(g_Ah + 4 * i) = *reinterpret_cast<uint2*>(h);
    *reinterpret_cast<uint2*>(g_Al + 4 * i) = *reinterpret_cast<uint2*>(l);
}

// Gather-mean per bucket -> g_Ah[1+r]/g_Al[1+r]
__global__ void agg_kernel(const float* __restrict__ X) {
    const int wid  = (blockIdx.x * blockDim.x + threadIdx.x) >> 5;
    const int lane = threadIdx.x & 31;
    if (wid >= NBUCKETS) return;

    const int deg   = g_deg[wid];
    const int start = g_off[wid];

    float s0[4] = {0.f, 0.f, 0.f, 0.f};
    float s1[4] = {0.f, 0.f, 0.f, 0.f};
    for (int e = 0; e < deg; ++e) {
        const int src = g_eidx[start + e];
        const float4* xr = reinterpret_cast<const float4*>(X + (size_t)src * C_DIM);
        const float4 v0 = xr[2 * lane];
        const float4 v1 = xr[2 * lane + 1];
        s0[0] += v0.x; s0[1] += v0.y; s0[2] += v0.z; s0[3] += v0.w;
        s1[0] += v1.x; s1[1] += v1.y; s1[2] += v1.z; s1[3] += v1.w;
    }
    const float inv = (deg > 0) ? (1.0f / (float)deg) : 0.0f;

    __nv_bfloat16 h[8], l[8];
    #pragma unroll
    for (int q = 0; q < 4; ++q) split1(s0[q] * inv, h[q], l[q]);
    #pragma unroll
    for (int q = 0; q < 4; ++q) split1(s1[q] * inv, h[4 + q], l[4 + q]);

    // bucket wid = r*N + node  ->  matrix slot m = 1 + r, row = node
    const size_t o = ((size_t)N_NODES * C_DIM) + (size_t)wid * C_DIM + lane * 8;
    *reinterpret_cast<uint4*>(g_Ah + o) = *reinterpret_cast<uint4*>(h);
    *reinterpret_cast<uint4*>(g_Al + o) = *reinterpret_cast<uint4*>(l);
}

// ---------------------------------------------------------------------------
// Dense GEMM (K=1280 concat, split-bf16 3-pass) + gate epilogue.
// Tile M=128 x N=256, 512 threads = 16 warps (8m x 2n). Double-buffered cp.async.
// ---------------------------------------------------------------------------
#define MB    128
#define KCH   32
#define NCHUNK 40
#define SAW   40      // A smem row stride (bf16)
#define SWW   264     // W smem row stride (bf16)
#define A_STAGE (2 * MB * SAW)        // 10240 bf16 (hi+lo)
#define W_STAGE (2 * KCH * SWW)       // 16896 bf16 (hi+lo)
#define W_BASE  (2 * A_STAGE)         // 20480
#define SMEM_BYTES ((W_BASE + 2 * W_STAGE) * 2)   // 108,544 B

__device__ __forceinline__ void cp16(void* dst_smem, const void* src) {
    unsigned int d = (unsigned int)__cvta_generic_to_shared(dst_smem);
    asm volatile("cp.async.cg.shared.global [%0], [%1], 16;" :: "r"(d), "l"(src));
}
__device__ __forceinline__ void ldsm4(const void* p, unsigned& r0, unsigned& r1,
                                      unsigned& r2, unsigned& r3) {
    unsigned a = (unsigned)__cvta_generic_to_shared(p);
    asm volatile("ldmatrix.sync.aligned.m8n8.x4.shared.b16 {%0,%1,%2,%3}, [%4];"
                 : "=r"(r0), "=r"(r1), "=r"(r2), "=r"(r3) : "r"(a));
}
__device__ __forceinline__ void ldsm4t(const void* p, unsigned& r0, unsigned& r1,
                                       unsigned& r2, unsigned& r3) {
    unsigned a = (unsigned)__cvta_generic_to_shared(p);
    asm volatile("ldmatrix.sync.aligned.m8n8.x4.trans.shared.b16 {%0,%1,%2,%3}, [%4];"
                 : "=r"(r0), "=r"(r1), "=r"(r2), "=r"(r3) : "r"(a));
}
__device__ __forceinline__ void mma16816(float* c, unsigned a0, unsigned a1,
                                         unsigned a2, unsigned a3,
                                         unsigned b0, unsigned b1) {
    asm volatile(
        "mma.sync.aligned.m16n8k16.row.col.f32.bf16.bf16.f32 "
        "{%0,%1,%2,%3}, {%4,%5,%6,%7}, {%8,%9}, {%0,%1,%2,%3};"
        : "+f"(c[0]), "+f"(c[1]), "+f"(c[2]), "+f"(c[3])
        : "r"(a0), "r"(a1), "r"(a2), "r"(a3), "r"(b0), "r"(b1));
}

__global__ void __launch_bounds__(512, 1) gemm_gate(
    const float* __restrict__ X,
    const float* __restrict__ bias,
    const float* __restrict__ attW,
    const float* __restrict__ attB,
    float* __restrict__ out)
{
    extern __shared__ char smem_raw[];
    __nv_bfloat16* sm = (__nv_bfloat16*)smem_raw;
    float* pa = (float*)smem_raw;       // epilogue overlay: part[128][2] + a_s[128]

    const int t    = threadIdx.x;
    const int lane = t & 31;
    const int warp = t >> 5;
    const int wm   = warp & 7;      // 8 m-warps x 16 rows
    const int wn   = warp >> 3;     // 2 n-warps x 128 cols
    const int node0 = blockIdx.x * MB;

    float acc[16][4];
    #pragma unroll
    for (int i = 0; i < 16; ++i)
        #pragma unroll
        for (int j = 0; j < 4; ++j) acc[i][j] = 0.f;

    // per-thread load coordinates
    const int a_row = t >> 2, a_seg = t & 3;          // A: 128 rows x 4 segs
    const int a_node = min(node0 + a_row, N_NODES - 1);

    auto load_chunk = [&](int c, int stage) {
        const int m  = c >> 3;
        const int k0 = (c & 7) * KCH;
        // A: hi + lo
        {
            const size_t g = ((size_t)m * N_NODES + a_node) * C_DIM + k0 + a_seg * 8;
            const int d = stage * A_STAGE + a_row * SAW + a_seg * 8;
            cp16(sm + d, g_Ah + g);
            cp16(sm + d + MB * SAW, g_Al + g);
        }
        // W: hi + lo (2 granules each per thread)
        #pragma unroll
        for (int i = 0; i < 2; ++i) {
            const int p = t + 512 * i;                 // 0..1023
            const int row = p >> 5, seg = p & 31;
            const size_t g = ((size_t)m * C_DIM + k0 + row) * C_DIM + seg * 8;
            const int d = W_BASE + stage * W_STAGE + row * SWW + seg * 8;
            cp16(sm + d, g_Wh + g);
            cp16(sm + d + KCH * SWW, g_Wl + g);
        }
        asm volatile("cp.async.commit_group;");
    };

    load_chunk(0, 0);

    for (int c = 0; c < NCHUNK; ++c) {
        const int stage = c & 1;
        if (c + 1 < NCHUNK) {
            load_chunk(c + 1, stage ^ 1);
            asm volatile("cp.async.wait_group 1;");
        } else {
            asm volatile("cp.async.wait_group 0;");
        }
        __syncthreads();

        const __nv_bfloat16* Ab = sm + stage * A_STAGE;
        const __nv_bfloat16* Wb = sm + W_BASE + stage * W_STAGE;

        #pragma unroll
        for (int s = 0; s < 2; ++s) {
            const __nv_bfloat16* ap =
                Ab + (wm * 16 + (lane & 15)) * SAW + s * 16 + (lane >> 4) * 8;
            unsigned ah0, ah1, ah2, ah3, al0, al1, al2, al3;
            ldsm4(ap, ah0, ah1, ah2, ah3);
            ldsm4(ap + MB * SAW, al0, al1, al2, al3);

            const int krow = s * 16 + (lane & 15);
            #pragma unroll
            for (int nt2 = 0; nt2 < 8; ++nt2) {
                const int ncol = wn * 128 + nt2 * 16 + (lane >> 4) * 8;
                unsigned bh0, bh1, bh2, bh3, bl0, bl1, bl2, bl3;
                ldsm4t(Wb + krow * SWW + ncol, bh0, bh1, bh2, bh3);
                ldsm4t(Wb + KCH * SWW + krow * SWW + ncol, bl0, bl1, bl2, bl3);
                float* c0 = acc[2 * nt2];
                float* c1 = acc[2 * nt2 + 1];
                mma16816(c0, ah0, ah1, ah2, ah3, bh0, bh1);
                mma16816(c1, ah0, ah1, ah2, ah3, bh2, bh3);
                mma16816(c0, al0, al1, al2, al3, bh0, bh1);
                mma16816(c1, al0, al1, al2, al3, bh2, bh3);
                mma16816(c0, ah0, ah1, ah2, ah3, bl0, bl1);
                mma16816(c1, ah0, ah1, ah2, ah3, bl2, bl3);
            }
        }
        __syncthreads();
    }

    // ---------------- epilogue (register-resident) ----------------
    // fragment: rows wm*16 + (lane>>2), +8 ; cols = base + 2*(lane&3) + {0,1}
    const int r0   = lane >> 2;
    const int cq   = 2 * (lane & 3);
    const int row0 = wm * 16 + r0;          // tile-local
    const int n0g  = node0 + row0;
    const int n1g  = n0g + 8;
    const bool v0  = n0g < N_NODES;
    const bool v1  = n1g < N_NODES;

    float pz0 = 0.f, pz1 = 0.f;
    #pragma unroll
    for (int nt = 0; nt < 16; ++nt) {
        const int col = wn * 128 + (nt >> 1) * 16 + (nt & 1) * 8 + cq;
        const float b0 = bias[col], b1 = bias[col + 1];
        const float wu0 = attW[col], wu1 = attW[col + 1];
        const float wx0 = attW[C_DIM + col], wx1 = attW[C_DIM + col + 1];
        pz0 += (acc[nt][0] + b0) * wu0 + (acc[nt][1] + b1) * wu1;
        pz1 += (acc[nt][2] + b0) * wu0 + (acc[nt][3] + b1) * wu1;
        if (v0) {
            const float2 x2 = *reinterpret_cast<const float2*>(X + (size_t)n0g * C_DIM + col);
            pz0 += x2.x * wx0 + x2.y * wx1;
        }
        if (v1) {
            const float2 x2 = *reinterpret_cast<const float2*>(X + (size_t)n1g * C_DIM + col);
            pz1 += x2.x * wx0 + x2.y * wx1;
        }
    }
    // reduce over the 4 lanes of each row-quad
    pz0 += __shfl_xor_sync(0xffffffffu, pz0, 1);
    pz0 += __shfl_xor_sync(0xffffffffu, pz0, 2);
    pz1 += __shfl_xor_sync(0xffffffffu, pz1, 1);
    pz1 += __shfl_xor_sync(0xffffffffu, pz1, 2);

    if ((lane & 3) == 0) {
        pa[row0 * 2 + wn]       = pz0;
        pa[(row0 + 8) * 2 + wn] = pz1;
    }
    __syncthreads();
    float* a_s = pa + 2 * MB;
    if (t < MB) {
        const float z = pa[t * 2] + pa[t * 2 + 1] + attB[0];
        a_s[t] = 1.0f / (1.0f + expf(-z));
    }
    __syncthreads();

    const float a0 = a_s[row0], a1 = a_s[row0 + 8];
    #pragma unroll
    for (int nt = 0; nt < 16; ++nt) {
        const int col = wn * 128 + (nt >> 1) * 16 + (nt & 1) * 8 + cq;
        const float b0 = bias[col], b1 = bias[col + 1];
        if (v0) {
            const float2 x2 = *reinterpret_cast<const float2*>(X + (size_t)n0g * C_DIM + col);
            float2 h;
            h.x = tanhf(acc[nt][0] + b0) * a0 + x2.x * (1.0f - a0);
            h.y = tanhf(acc[nt][1] + b1) * a0 + x2.y * (1.0f - a0);
            *reinterpret_cast<float2*>(out + (size_t)n0g * C_DIM + col) = h;
        }
        if (v1) {
            const float2 x2 = *reinterpret_cast<const float2*>(X + (size_t)n1g * C_DIM + col);
            float2 h;
            h.x = tanhf(acc[nt][2] + b0) * a1 + x2.x * (1.0f - a1);
            h.y = tanhf(acc[nt][3] + b1) * a1 + x2.y * (1.0f - a1);
            *reinterpret_cast<float2*>(out + (size_t)n1g * C_DIM + col) = h;
        }
    }
}

// ---------------------------------------------------------------------------
// Launch
// ---------------------------------------------------------------------------
extern "C" void kernel_launch(void* const* d_in, const int* in_sizes, int n_in,
                              void* d_out, int out_size) {
    const float* X     = (const float*)d_in[0];
    const int*   ei    = (const int*)d_in[1];     // int32
    const int*   et    = (const int*)d_in[2];     // int32
    const float* relW  = (const float*)d_in[3];
    const float* rootW = (const float*)d_in[4];
    const float* bias  = (const float*)d_in[5];
    const float* attW  = (const float*)d_in[6];
    const float* attB  = (const float*)d_in[7];
    float*       out   = (float*)d_out;
    (void)in_sizes; (void)n_in; (void)out_size;

    cudaFuncSetAttribute(gemm_gate,
                         cudaFuncAttributeMaxDynamicSharedMemorySize, SMEM_BYTES);

    zero_counts_kernel<<<(NBUCKETS + 255) / 256, 256>>>();
    hist_kernel<<<(N_EDGES + 255) / 256, 256>>>(ei, et);
    wsplit_kernel<<<(5 * C_DIM * C_DIM + 255) / 256, 256>>>(relW, rootW);
    xsplit_kernel<<<(N_NODES * C_DIM / 4 + 255) / 256, 256>>>(X);
    scan_blocks_kernel<<<NSCANBLK, SCAN_BS>>>();
    scan_top_kernel<<<1, 256>>>();
    scan_add_kernel<<<(NBUCKETS + 255) / 256, 256>>>();
    bucket_kernel<<<(N_EDGES + 255) / 256, 256>>>(ei, et);
    agg_kernel<<<(NBUCKETS * 32 + 255) / 256, 256>>>(X);
    gemm_gate<<<(N_NODES + MB - 1) / MB, 512, SMEM_BYTES>>>(X, bias, attW, attB, out);
}

// round 9
// speedup vs baseline: 2.2994x; 1.2222x over previous
#include <cuda_runtime.h>
#include <cuda_fp16.h>
#include <cstdint>
#include <cstddef>

#define N_NODES   50000
#define N_EDGES   800000
#define C_DIM     256
#define R_REL     4
#define NBUCKETS  (R_REL * N_NODES)
#define SCAN_BS   1024
#define NSCANBLK  ((NBUCKETS + SCAN_BS - 1) / SCAN_BS)

// -------------------- scratch --------------------
__device__ int g_deg[NBUCKETS];
__device__ int g_off[NBUCKETS];
__device__ int g_cursor[NBUCKETS];
__device__ int g_eidx[N_EDGES];
__device__ int g_bsum[SCAN_BS];
__device__ int g_bsumx[SCAN_BS];
// fp16 weights [5][256][256] in [k][n] layout (root, rel0..3)
__device__ __half g_W[5 * C_DIM * C_DIM];
// fp16 split A operand [5][N][256]: m=0 -> X, m=1..4 -> per-relation means
__device__ __half g_Ah[(size_t)5 * N_NODES * C_DIM];
__device__ __half g_Al[(size_t)5 * N_NODES * C_DIM];

__device__ __forceinline__ bool edge_ok(int s, int d, int r) {
    return ((unsigned)s < (unsigned)N_NODES) &&
           ((unsigned)d < (unsigned)N_NODES) &&
           ((unsigned)r < (unsigned)R_REL);
}

// ---------------------------------------------------------------------------
// CSR build (edges are INT32)
// ---------------------------------------------------------------------------
__global__ void zero_counts_kernel() {
    int i = blockIdx.x * blockDim.x + threadIdx.x;
    if (i < NBUCKETS) { g_deg[i] = 0; g_cursor[i] = 0; }
}

__global__ void hist_kernel(const int* __restrict__ edge_index,
                            const int* __restrict__ edge_type) {
    int e = blockIdx.x * blockDim.x + threadIdx.x;
    if (e >= N_EDGES) return;
    int s = edge_index[e];
    int d = edge_index[N_EDGES + e];
    int r = edge_type[e];
    if (!edge_ok(s, d, r)) return;
    atomicAdd(&g_deg[r * N_NODES + d], 1);
}

__global__ void scan_blocks_kernel() {
    __shared__ int sh[SCAN_BS];
    const int tid = threadIdx.x;
    const int gid = blockIdx.x * SCAN_BS + tid;
    int v = (gid < NBUCKETS) ? g_deg[gid] : 0;
    sh[tid] = v;
    __syncthreads();
    for (int o = 1; o < SCAN_BS; o <<= 1) {
        int t = (tid >= o) ? sh[tid - o] : 0;
        __syncthreads();
        sh[tid] += t;
        __syncthreads();
    }
    int incl = sh[tid];
    if (gid < NBUCKETS) g_off[gid] = incl - v;
    if (tid == SCAN_BS - 1) g_bsum[blockIdx.x] = incl;
}

__global__ void scan_top_kernel() {
    __shared__ int sh[256];
    const int tid = threadIdx.x;
    int v = (tid < NSCANBLK) ? g_bsum[tid] : 0;
    sh[tid] = v;
    __syncthreads();
    for (int o = 1; o < 256; o <<= 1) {
        int t = (tid >= o) ? sh[tid - o] : 0;
        __syncthreads();
        sh[tid] += t;
        __syncthreads();
    }
    g_bsumx[tid] = sh[tid] - v;
}

__global__ void scan_add_kernel() {
    int i = blockIdx.x * blockDim.x + threadIdx.x;
    if (i < NBUCKETS) g_off[i] += g_bsumx[i >> 10];
}

__global__ void bucket_kernel(const int* __restrict__ edge_index,
                              const int* __restrict__ edge_type) {
    int e = blockIdx.x * blockDim.x + threadIdx.x;
    if (e >= N_EDGES) return;
    int s = edge_index[e];
    int d = edge_index[N_EDGES + e];
    int r = edge_type[e];
    if (!edge_ok(s, d, r)) return;
    int b = r * N_NODES + d;
    int pos = g_off[b] + atomicAdd(&g_cursor[b], 1);
    if ((unsigned)pos < (unsigned)N_EDGES)
        g_eidx[pos] = s;
}

// ---------------------------------------------------------------------------
// Splits (fp16)
// ---------------------------------------------------------------------------
__device__ __forceinline__ void split1h(float v, __half& h, __half& l) {
    h = __float2half(v);
    l = __float2half(v - __half2float(h));
}

// W -> fp16 [m][k][n]
__global__ void wconv_kernel(const float* __restrict__ relW,
                             const float* __restrict__ rootW) {
    int i = blockIdx.x * blockDim.x + threadIdx.x;
    if (i >= 5 * C_DIM * C_DIM) return;
    int m = i >> 16;
    int o = i & 65535;
    float v = (m == 0) ? rootW[o] : relW[(size_t)(m - 1) * C_DIM * C_DIM + o];
    g_W[i] = __float2half(v);
}

// X -> g_Ah[0]/g_Al[0]
__global__ void xsplit_kernel(const float* __restrict__ X) {
    size_t i = (size_t)blockIdx.x * blockDim.x + threadIdx.x;   // float4 index
    if (i >= (size_t)N_NODES * C_DIM / 4) return;
    float4 v = reinterpret_cast<const float4*>(X)[i];
    __half h[4], l[4];
    split1h(v.x, h[0], l[0]); split1h(v.y, h[1], l[1]);
    split1h(v.z, h[2], l[2]); split1h(v.w, h[3], l[3]);
    *reinterpret_cast<uint2*>(g_Ah + 4 * i) = *reinterpret_cast<uint2*>(h);
    *reinterpret_cast<uint2*>(g_Al + 4 * i) = *reinterpret_cast<uint2*>(l);
}

// Gather-mean per bucket -> g_Ah[1+r]/g_Al[1+r]
__global__ void agg_kernel(const float* __restrict__ X) {
    const int wid  = (blockIdx.x * blockDim.x + threadIdx.x) >> 5;
    const int lane = threadIdx.x & 31;
    if (wid >= NBUCKETS) return;

    const int deg   = g_deg[wid];
    const int start = g_off[wid];

    float s0[4] = {0.f, 0.f, 0.f, 0.f};
    float s1[4] = {0.f, 0.f, 0.f, 0.f};
    for (int e = 0; e < deg; ++e) {
        const int src = g_eidx[start + e];
        const float4* xr = reinterpret_cast<const float4*>(X + (size_t)src * C_DIM);
        const float4 v0 = xr[2 * lane];
        const float4 v1 = xr[2 * lane + 1];
        s0[0] += v0.x; s0[1] += v0.y; s0[2] += v0.z; s0[3] += v0.w;
        s1[0] += v1.x; s1[1] += v1.y; s1[2] += v1.z; s1[3] += v1.w;
    }
    const float inv = (deg > 0) ? (1.0f / (float)deg) : 0.0f;

    __half h[8], l[8];
    #pragma unroll
    for (int q = 0; q < 4; ++q) split1h(s0[q] * inv, h[q], l[q]);
    #pragma unroll
    for (int q = 0; q < 4; ++q) split1h(s1[q] * inv, h[4 + q], l[4 + q]);

    const size_t o = ((size_t)N_NODES * C_DIM) + (size_t)wid * C_DIM + lane * 8;
    *reinterpret_cast<uint4*>(g_Ah + o) = *reinterpret_cast<uint4*>(h);
    *reinterpret_cast<uint4*>(g_Al + o) = *reinterpret_cast<uint4*>(l);
}

// ---------------------------------------------------------------------------
// Dense GEMM (K=1280 concat, A-split fp16 2-pass) + gate epilogue.
// Tile M=128 x N=256, 512 threads = 16 warps (8m x 2n). 3-stage cp.async.
// ---------------------------------------------------------------------------
#define MB      128
#define KCH     32
#define NCHUNK  40
#define SAW     40      // A smem row stride (half)
#define SWW     264     // W smem row stride (half)
#define A_STAGE (2 * MB * SAW)          // 10240 half (hi+lo)
#define W_STAGE (KCH * SWW)             // 8448 half
#define STAGE_H (A_STAGE + W_STAGE)     // 18688 half
#define SMEM_BYTES (3 * STAGE_H * 2)    // 112,128 B

__device__ __forceinline__ void cp16(void* dst_smem, const void* src) {
    unsigned int d = (unsigned int)__cvta_generic_to_shared(dst_smem);
    asm volatile("cp.async.cg.shared.global [%0], [%1], 16;" :: "r"(d), "l"(src));
}
__device__ __forceinline__ void ldsm4(const void* p, unsigned& r0, unsigned& r1,
                                      unsigned& r2, unsigned& r3) {
    unsigned a = (unsigned)__cvta_generic_to_shared(p);
    asm volatile("ldmatrix.sync.aligned.m8n8.x4.shared.b16 {%0,%1,%2,%3}, [%4];"
                 : "=r"(r0), "=r"(r1), "=r"(r2), "=r"(r3) : "r"(a));
}
__device__ __forceinline__ void ldsm4t(const void* p, unsigned& r0, unsigned& r1,
                                       unsigned& r2, unsigned& r3) {
    unsigned a = (unsigned)__cvta_generic_to_shared(p);
    asm volatile("ldmatrix.sync.aligned.m8n8.x4.trans.shared.b16 {%0,%1,%2,%3}, [%4];"
                 : "=r"(r0), "=r"(r1), "=r"(r2), "=r"(r3) : "r"(a));
}
__device__ __forceinline__ void mma16816(float* c, unsigned a0, unsigned a1,
                                         unsigned a2, unsigned a3,
                                         unsigned b0, unsigned b1) {
    asm volatile(
        "mma.sync.aligned.m16n8k16.row.col.f32.f16.f16.f32 "
        "{%0,%1,%2,%3}, {%4,%5,%6,%7}, {%8,%9}, {%0,%1,%2,%3};"
        : "+f"(c[0]), "+f"(c[1]), "+f"(c[2]), "+f"(c[3])
        : "r"(a0), "r"(a1), "r"(a2), "r"(a3), "r"(b0), "r"(b1));
}

__global__ void __launch_bounds__(512, 1) gemm_gate(
    const float* __restrict__ X,
    const float* __restrict__ bias,
    const float* __restrict__ attW,
    const float* __restrict__ attB,
    float* __restrict__ out)
{
    extern __shared__ char smem_raw[];
    __half* sm = (__half*)smem_raw;
    float* pa = (float*)smem_raw;       // epilogue overlay

    const int t    = threadIdx.x;
    const int lane = t & 31;
    const int warp = t >> 5;
    const int wm   = warp & 7;      // 8 m-warps x 16 rows
    const int wn   = warp >> 3;     // 2 n-warps x 128 cols
    const int node0 = blockIdx.x * MB;

    float acc[16][4];
    #pragma unroll
    for (int i = 0; i < 16; ++i)
        #pragma unroll
        for (int j = 0; j < 4; ++j) acc[i][j] = 0.f;

    const int a_row = t >> 2, a_seg = t & 3;
    const int a_node = min(node0 + a_row, N_NODES - 1);

    auto load_chunk = [&](int c, int stage) {
        const int m  = c >> 3;
        const int k0 = (c & 7) * KCH;
        __half* st = sm + stage * STAGE_H;
        // A hi + lo (16B each)
        {
            const size_t g = ((size_t)m * N_NODES + a_node) * C_DIM + k0 + a_seg * 8;
            const int d = a_row * SAW + a_seg * 8;
            cp16(st + d, g_Ah + g);
            cp16(st + MB * SAW + d, g_Al + g);
        }
        // W (2 granules per thread)
        #pragma unroll
        for (int i = 0; i < 2; ++i) {
            const int p = t + 512 * i;                 // 0..1023
            const int row = p >> 5, seg = p & 31;
            const size_t g = ((size_t)m * C_DIM + k0 + row) * C_DIM + seg * 8;
            cp16(st + A_STAGE + row * SWW + seg * 8, g_W + g);
        }
        asm volatile("cp.async.commit_group;");
    };

    load_chunk(0, 0);
    load_chunk(1, 1);

    for (int c = 0; c < NCHUNK; ++c) {
        if (c + 1 < NCHUNK) asm volatile("cp.async.wait_group 1;");
        else                asm volatile("cp.async.wait_group 0;");
        __syncthreads();   // stage c visible; stage (c-1)%3 consumers done

        if (c + 2 < NCHUNK) load_chunk(c + 2, (c + 2) % 3);

        const __half* st = sm + (c % 3) * STAGE_H;
        const __half* Wb = st + A_STAGE;

        #pragma unroll
        for (int s = 0; s < 2; ++s) {
            const __half* ap =
                st + (wm * 16 + (lane & 15)) * SAW + s * 16 + (lane >> 4) * 8;
            unsigned ah0, ah1, ah2, ah3, al0, al1, al2, al3;
            ldsm4(ap, ah0, ah1, ah2, ah3);
            ldsm4(ap + MB * SAW, al0, al1, al2, al3);

            const int krow = s * 16 + (lane & 15);
            #pragma unroll
            for (int nt2 = 0; nt2 < 8; ++nt2) {
                const int ncol = wn * 128 + nt2 * 16 + (lane >> 4) * 8;
                unsigned b0, b1, b2, b3;
                ldsm4t(Wb + krow * SWW + ncol, b0, b1, b2, b3);
                float* c0 = acc[2 * nt2];
                float* c1 = acc[2 * nt2 + 1];
                mma16816(c0, ah0, ah1, ah2, ah3, b0, b1);
                mma16816(c1, ah0, ah1, ah2, ah3, b2, b3);
                mma16816(c0, al0, al1, al2, al3, b0, b1);
                mma16816(c1, al0, al1, al2, al3, b2, b3);
            }
        }
    }
    __syncthreads();   // all computes done before smem overlay

    // ---------------- epilogue (register-resident) ----------------
    const int r0   = lane >> 2;
    const int cq   = 2 * (lane & 3);
    const int row0 = wm * 16 + r0;
    const int n0g  = node0 + row0;
    const int n1g  = n0g + 8;
    const bool v0  = n0g < N_NODES;
    const bool v1  = n1g < N_NODES;

    float pz0 = 0.f, pz1 = 0.f;
    #pragma unroll
    for (int nt = 0; nt < 16; ++nt) {
        const int col = wn * 128 + (nt >> 1) * 16 + (nt & 1) * 8 + cq;
        const float b0 = bias[col], b1 = bias[col + 1];
        const float wu0 = attW[col], wu1 = attW[col + 1];
        const float wx0 = attW[C_DIM + col], wx1 = attW[C_DIM + col + 1];
        pz0 += (acc[nt][0] + b0) * wu0 + (acc[nt][1] + b1) * wu1;
        pz1 += (acc[nt][2] + b0) * wu0 + (acc[nt][3] + b1) * wu1;
        if (v0) {
            const float2 x2 = *reinterpret_cast<const float2*>(X + (size_t)n0g * C_DIM + col);
            pz0 += x2.x * wx0 + x2.y * wx1;
        }
        if (v1) {
            const float2 x2 = *reinterpret_cast<const float2*>(X + (size_t)n1g * C_DIM + col);
            pz1 += x2.x * wx0 + x2.y * wx1;
        }
    }
    pz0 += __shfl_xor_sync(0xffffffffu, pz0, 1);
    pz0 += __shfl_xor_sync(0xffffffffu, pz0, 2);
    pz1 += __shfl_xor_sync(0xffffffffu, pz1, 1);
    pz1 += __shfl_xor_sync(0xffffffffu, pz1, 2);

    if ((lane & 3) == 0) {
        pa[row0 * 2 + wn]       = pz0;
        pa[(row0 + 8) * 2 + wn] = pz1;
    }
    __syncthreads();
    float* a_s = pa + 2 * MB;
    if (t < MB) {
        const float z = pa[t * 2] + pa[t * 2 + 1] + attB[0];
        a_s[t] = 1.0f / (1.0f + expf(-z));
    }
    __syncthreads();

    const float a0 = a_s[row0], a1 = a_s[row0 + 8];
    #pragma unroll
    for (int nt = 0; nt < 16; ++nt) {
        const int col = wn * 128 + (nt >> 1) * 16 + (nt & 1) * 8 + cq;
        const float b0 = bias[col], b1 = bias[col + 1];
        if (v0) {
            const float2 x2 = *reinterpret_cast<const float2*>(X + (size_t)n0g * C_DIM + col);
            float2 h;
            h.x = tanhf(acc[nt][0] + b0) * a0 + x2.x * (1.0f - a0);
            h.y = tanhf(acc[nt][1] + b1) * a0 + x2.y * (1.0f - a0);
            *reinterpret_cast<float2*>(out + (size_t)n0g * C_DIM + col) = h;
        }
        if (v1) {
            const float2 x2 = *reinterpret_cast<const float2*>(X + (size_t)n1g * C_DIM + col);
            float2 h;
            h.x = tanhf(acc[nt][2] + b0) * a1 + x2.x * (1.0f - a1);
            h.y = tanhf(acc[nt][3] + b1) * a1 + x2.y * (1.0f - a1);
            *reinterpret_cast<float2*>(out + (size_t)n1g * C_DIM + col) = h;
        }
    }
}

// ---------------------------------------------------------------------------
// Launch
// ---------------------------------------------------------------------------
extern "C" void kernel_launch(void* const* d_in, const int* in_sizes, int n_in,
                              void* d_out, int out_size) {
    const float* X     = (const float*)d_in[0];
    const int*   ei    = (const int*)d_in[1];     // int32
    const int*   et    = (const int*)d_in[2];     // int32
    const float* relW  = (const float*)d_in[3];
    const float* rootW = (const float*)d_in[4];
    const float* bias  = (const float*)d_in[5];
    const float* attW  = (const float*)d_in[6];
    const float* attB  = (const float*)d_in[7];
    float*       out   = (float*)d_out;
    (void)in_sizes; (void)n_in; (void)out_size;

    cudaFuncSetAttribute(gemm_gate,
                         cudaFuncAttributeMaxDynamicSharedMemorySize, SMEM_BYTES);

    zero_counts_kernel<<<(NBUCKETS + 255) / 256, 256>>>();
    hist_kernel<<<(N_EDGES + 255) / 256, 256>>>(ei, et);
    wconv_kernel<<<(5 * C_DIM * C_DIM + 255) / 256, 256>>>(relW, rootW);
    xsplit_kernel<<<(N_NODES * C_DIM / 4 + 255) / 256, 256>>>(X);
    scan_blocks_kernel<<<NSCANBLK, SCAN_BS>>>();
    scan_top_kernel<<<1, 256>>>();
    scan_add_kernel<<<(NBUCKETS + 255) / 256, 256>>>();
    bucket_kernel<<<(N_EDGES + 255) / 256, 256>>>(ei, et);
    agg_kernel<<<(NBUCKETS * 32 + 255) / 256, 256>>>(X);
    gemm_gate<<<(N_NODES + MB - 1) / MB, 512, SMEM_BYTES>>>(X, bias, attW, attB, out);
}

// round 10
// speedup vs baseline: 3.2380x; 1.4082x over previous
#include <cuda_runtime.h>
#include <cuda_fp16.h>
#include <cstdint>
#include <cstddef>

#define N_NODES   50000
#define N_EDGES   800000
#define C_DIM     256
#define R_REL     4
#define NBUCKETS  (R_REL * N_NODES)
#define SCAN_BS   1024
#define NSCANBLK  ((NBUCKETS + SCAN_BS - 1) / SCAN_BS)

// -------------------- scratch --------------------
__device__ int g_deg[NBUCKETS];
__device__ int g_off[NBUCKETS];
__device__ int g_cursor[NBUCKETS];
__device__ int g_eidx[N_EDGES];
__device__ int g_bsum[SCAN_BS];
__device__ int g_bsumx[SCAN_BS];
// fp16 weights [5][256][256] in [k][n] layout (root, rel0..3)
__device__ __half g_W[5 * C_DIM * C_DIM];
// fp16 A operand [5][N][256]: m=0 -> X(fp16), m=1..4 -> per-relation means
__device__ __half g_A[(size_t)5 * N_NODES * C_DIM];

__device__ __forceinline__ bool edge_ok(int s, int d, int r) {
    return ((unsigned)s < (unsigned)N_NODES) &&
           ((unsigned)d < (unsigned)N_NODES) &&
           ((unsigned)r < (unsigned)R_REL);
}

// ---------------------------------------------------------------------------
// CSR build (edges are INT32)
// ---------------------------------------------------------------------------
__global__ void zero_counts_kernel() {
    int i = blockIdx.x * blockDim.x + threadIdx.x;
    if (i < NBUCKETS) { g_deg[i] = 0; g_cursor[i] = 0; }
}

__global__ void hist_kernel(const int* __restrict__ edge_index,
                            const int* __restrict__ edge_type) {
    int e = blockIdx.x * blockDim.x + threadIdx.x;
    if (e >= N_EDGES) return;
    int s = edge_index[e];
    int d = edge_index[N_EDGES + e];
    int r = edge_type[e];
    if (!edge_ok(s, d, r)) return;
    atomicAdd(&g_deg[r * N_NODES + d], 1);
}

__global__ void scan_blocks_kernel() {
    __shared__ int sh[SCAN_BS];
    const int tid = threadIdx.x;
    const int gid = blockIdx.x * SCAN_BS + tid;
    int v = (gid < NBUCKETS) ? g_deg[gid] : 0;
    sh[tid] = v;
    __syncthreads();
    for (int o = 1; o < SCAN_BS; o <<= 1) {
        int t = (tid >= o) ? sh[tid - o] : 0;
        __syncthreads();
        sh[tid] += t;
        __syncthreads();
    }
    int incl = sh[tid];
    if (gid < NBUCKETS) g_off[gid] = incl - v;
    if (tid == SCAN_BS - 1) g_bsum[blockIdx.x] = incl;
}

__global__ void scan_top_kernel() {
    __shared__ int sh[256];
    const int tid = threadIdx.x;
    int v = (tid < NSCANBLK) ? g_bsum[tid] : 0;
    sh[tid] = v;
    __syncthreads();
    for (int o = 1; o < 256; o <<= 1) {
        int t = (tid >= o) ? sh[tid - o] : 0;
        __syncthreads();
        sh[tid] += t;
        __syncthreads();
    }
    g_bsumx[tid] = sh[tid] - v;
}

__global__ void scan_add_kernel() {
    int i = blockIdx.x * blockDim.x + threadIdx.x;
    if (i < NBUCKETS) g_off[i] += g_bsumx[i >> 10];
}

__global__ void bucket_kernel(const int* __restrict__ edge_index,
                              const int* __restrict__ edge_type) {
    int e = blockIdx.x * blockDim.x + threadIdx.x;
    if (e >= N_EDGES) return;
    int s = edge_index[e];
    int d = edge_index[N_EDGES + e];
    int r = edge_type[e];
    if (!edge_ok(s, d, r)) return;
    int b = r * N_NODES + d;
    int pos = g_off[b] + atomicAdd(&g_cursor[b], 1);
    if ((unsigned)pos < (unsigned)N_EDGES)
        g_eidx[pos] = s;
}

// ---------------------------------------------------------------------------
// Conversions
// ---------------------------------------------------------------------------
// W -> fp16 [m][k][n]
__global__ void wconv_kernel(const float* __restrict__ relW,
                             const float* __restrict__ rootW) {
    int i = blockIdx.x * blockDim.x + threadIdx.x;
    if (i >= 5 * C_DIM * C_DIM) return;
    int m = i >> 16;
    int o = i & 65535;
    float v = (m == 0) ? rootW[o] : relW[(size_t)(m - 1) * C_DIM * C_DIM + o];
    g_W[i] = __float2half(v);
}

// X -> g_A slot 0 (fp16)
__global__ void xconv_kernel(const float* __restrict__ X) {
    size_t i = (size_t)blockIdx.x * blockDim.x + threadIdx.x;   // float4 index
    if (i >= (size_t)N_NODES * C_DIM / 4) return;
    float4 v = reinterpret_cast<const float4*>(X)[i];
    __half h[4];
    h[0] = __float2half(v.x); h[1] = __float2half(v.y);
    h[2] = __float2half(v.z); h[3] = __float2half(v.w);
    *reinterpret_cast<uint2*>(g_A + 4 * i) = *reinterpret_cast<uint2*>(h);
}

// Gather-mean per bucket over fp16 X -> g_A[1+r]
__global__ void agg_kernel() {
    const int wid  = (blockIdx.x * blockDim.x + threadIdx.x) >> 5;
    const int lane = threadIdx.x & 31;
    if (wid >= NBUCKETS) return;

    const int deg   = g_deg[wid];
    const int start = g_off[wid];

    float s[8] = {0.f, 0.f, 0.f, 0.f, 0.f, 0.f, 0.f, 0.f};
    for (int e = 0; e < deg; ++e) {
        const int src = g_eidx[start + e];
        // one uint4 = 8 halves per lane covers the whole 256-wide row
        const uint4 raw = *reinterpret_cast<const uint4*>(
            g_A + (size_t)src * C_DIM + lane * 8);
        const __half2* hp = reinterpret_cast<const __half2*>(&raw);
        #pragma unroll
        for (int q = 0; q < 4; ++q) {
            const float2 f = __half22float2(hp[q]);
            s[2 * q]     += f.x;
            s[2 * q + 1] += f.y;
        }
    }
    const float inv = (deg > 0) ? (1.0f / (float)deg) : 0.0f;

    __half h[8];
    #pragma unroll
    for (int q = 0; q < 8; ++q) h[q] = __float2half(s[q] * inv);

    const size_t o = ((size_t)N_NODES * C_DIM) + (size_t)wid * C_DIM + lane * 8;
    *reinterpret_cast<uint4*>(g_A + o) = *reinterpret_cast<uint4*>(h);
}

// ---------------------------------------------------------------------------
// Dense GEMM (K=1280 concat, single-pass fp16) + gate epilogue.
// Tile M=128 x N=256, 512 threads = 16 warps (8m x 2n). 3-stage cp.async.
// ---------------------------------------------------------------------------
#define MB      128
#define KCH     32
#define NCHUNK  40
#define SAW     40      // A smem row stride (half)
#define SWW     264     // W smem row stride (half)
#define A_STAGE (MB * SAW)              // 5120 half
#define W_STAGE (KCH * SWW)             // 8448 half
#define STAGE_H (A_STAGE + W_STAGE)     // 13568 half
#define SMEM_BYTES (3 * STAGE_H * 2)    // 81,408 B

__device__ __forceinline__ void cp16(void* dst_smem, const void* src) {
    unsigned int d = (unsigned int)__cvta_generic_to_shared(dst_smem);
    asm volatile("cp.async.cg.shared.global [%0], [%1], 16;" :: "r"(d), "l"(src));
}
__device__ __forceinline__ void ldsm4(const void* p, unsigned& r0, unsigned& r1,
                                      unsigned& r2, unsigned& r3) {
    unsigned a = (unsigned)__cvta_generic_to_shared(p);
    asm volatile("ldmatrix.sync.aligned.m8n8.x4.shared.b16 {%0,%1,%2,%3}, [%4];"
                 : "=r"(r0), "=r"(r1), "=r"(r2), "=r"(r3) : "r"(a));
}
__device__ __forceinline__ void ldsm4t(const void* p, unsigned& r0, unsigned& r1,
                                       unsigned& r2, unsigned& r3) {
    unsigned a = (unsigned)__cvta_generic_to_shared(p);
    asm volatile("ldmatrix.sync.aligned.m8n8.x4.trans.shared.b16 {%0,%1,%2,%3}, [%4];"
                 : "=r"(r0), "=r"(r1), "=r"(r2), "=r"(r3) : "r"(a));
}
__device__ __forceinline__ void mma16816(float* c, unsigned a0, unsigned a1,
                                         unsigned a2, unsigned a3,
                                         unsigned b0, unsigned b1) {
    asm volatile(
        "mma.sync.aligned.m16n8k16.row.col.f32.f16.f16.f32 "
        "{%0,%1,%2,%3}, {%4,%5,%6,%7}, {%8,%9}, {%0,%1,%2,%3};"
        : "+f"(c[0]), "+f"(c[1]), "+f"(c[2]), "+f"(c[3])
        : "r"(a0), "r"(a1), "r"(a2), "r"(a3), "r"(b0), "r"(b1));
}

__global__ void __launch_bounds__(512, 1) gemm_gate(
    const float* __restrict__ X,
    const float* __restrict__ bias,
    const float* __restrict__ attW,
    const float* __restrict__ attB,
    float* __restrict__ out)
{
    extern __shared__ char smem_raw[];
    __half* sm = (__half*)smem_raw;
    float* pa = (float*)smem_raw;       // epilogue overlay

    const int t    = threadIdx.x;
    const int lane = t & 31;
    const int warp = t >> 5;
    const int wm   = warp & 7;      // 8 m-warps x 16 rows
    const int wn   = warp >> 3;     // 2 n-warps x 128 cols
    const int node0 = blockIdx.x * MB;

    float acc[16][4];
    #pragma unroll
    for (int i = 0; i < 16; ++i)
        #pragma unroll
        for (int j = 0; j < 4; ++j) acc[i][j] = 0.f;

    const int a_row = t >> 2, a_seg = t & 3;
    const int a_node = min(node0 + a_row, N_NODES - 1);

    auto load_chunk = [&](int c, int stage) {
        const int m  = c >> 3;
        const int k0 = (c & 7) * KCH;
        __half* st = sm + stage * STAGE_H;
        // A: one 16B granule per thread (128 rows x 4 segs)
        {
            const size_t g = ((size_t)m * N_NODES + a_node) * C_DIM + k0 + a_seg * 8;
            cp16(st + a_row * SAW + a_seg * 8, g_A + g);
        }
        // W: 2 granules per thread
        #pragma unroll
        for (int i = 0; i < 2; ++i) {
            const int p = t + 512 * i;                 // 0..1023
            const int row = p >> 5, seg = p & 31;
            const size_t g = ((size_t)m * C_DIM + k0 + row) * C_DIM + seg * 8;
            cp16(st + A_STAGE + row * SWW + seg * 8, g_W + g);
        }
        asm volatile("cp.async.commit_group;");
    };

    load_chunk(0, 0);
    load_chunk(1, 1);

    for (int c = 0; c < NCHUNK; ++c) {
        if (c + 1 < NCHUNK) asm volatile("cp.async.wait_group 1;");
        else                asm volatile("cp.async.wait_group 0;");
        __syncthreads();   // stage c visible; stage (c-1)%3 consumers done

        if (c + 2 < NCHUNK) load_chunk(c + 2, (c + 2) % 3);

        const __half* st = sm + (c % 3) * STAGE_H;
        const __half* Wb = st + A_STAGE;

        #pragma unroll
        for (int s = 0; s < 2; ++s) {
            const __half* ap =
                st + (wm * 16 + (lane & 15)) * SAW + s * 16 + (lane >> 4) * 8;
            unsigned a0, a1, a2, a3;
            ldsm4(ap, a0, a1, a2, a3);

            const int krow = s * 16 + (lane & 15);
            #pragma unroll
            for (int nt2 = 0; nt2 < 8; ++nt2) {
                const int ncol = wn * 128 + nt2 * 16 + (lane >> 4) * 8;
                unsigned b0, b1, b2, b3;
                ldsm4t(Wb + krow * SWW + ncol, b0, b1, b2, b3);
                mma16816(acc[2 * nt2],     a0, a1, a2, a3, b0, b1);
                mma16816(acc[2 * nt2 + 1], a0, a1, a2, a3, b2, b3);
            }
        }
    }
    __syncthreads();   // all computes done before smem overlay

    // ---------------- epilogue (register-resident) ----------------
    const int r0   = lane >> 2;
    const int cq   = 2 * (lane & 3);
    const int row0 = wm * 16 + r0;
    const int n0g  = node0 + row0;
    const int n1g  = n0g + 8;
    const bool v0  = n0g < N_NODES;
    const bool v1  = n1g < N_NODES;

    float pz0 = 0.f, pz1 = 0.f;
    #pragma unroll
    for (int nt = 0; nt < 16; ++nt) {
        const int col = wn * 128 + (nt >> 1) * 16 + (nt & 1) * 8 + cq;
        const float b0 = bias[col], b1 = bias[col + 1];
        const float wu0 = attW[col], wu1 = attW[col + 1];
        const float wx0 = attW[C_DIM + col], wx1 = attW[C_DIM + col + 1];
        pz0 += (acc[nt][0] + b0) * wu0 + (acc[nt][1] + b1) * wu1;
        pz1 += (acc[nt][2] + b0) * wu0 + (acc[nt][3] + b1) * wu1;
        if (v0) {
            const float2 x2 = *reinterpret_cast<const float2*>(X + (size_t)n0g * C_DIM + col);
            pz0 += x2.x * wx0 + x2.y * wx1;
        }
        if (v1) {
            const float2 x2 = *reinterpret_cast<const float2*>(X + (size_t)n1g * C_DIM + col);
            pz1 += x2.x * wx0 + x2.y * wx1;
        }
    }
    pz0 += __shfl_xor_sync(0xffffffffu, pz0, 1);
    pz0 += __shfl_xor_sync(0xffffffffu, pz0, 2);
    pz1 += __shfl_xor_sync(0xffffffffu, pz1, 1);
    pz1 += __shfl_xor_sync(0xffffffffu, pz1, 2);

    if ((lane & 3) == 0) {
        pa[row0 * 2 + wn]       = pz0;
        pa[(row0 + 8) * 2 + wn] = pz1;
    }
    __syncthreads();
    float* a_s = pa + 2 * MB;
    if (t < MB) {
        const float z = pa[t * 2] + pa[t * 2 + 1] + attB[0];
        a_s[t] = 1.0f / (1.0f + expf(-z));
    }
    __syncthreads();

    const float a0 = a_s[row0], a1 = a_s[row0 + 8];
    #pragma unroll
    for (int nt = 0; nt < 16; ++nt) {
        const int col = wn * 128 + (nt >> 1) * 16 + (nt & 1) * 8 + cq;
        const float b0 = bias[col], b1 = bias[col + 1];
        if (v0) {
            const float2 x2 = *reinterpret_cast<const float2*>(X + (size_t)n0g * C_DIM + col);
            float2 h;
            h.x = tanhf(acc[nt][0] + b0) * a0 + x2.x * (1.0f - a0);
            h.y = tanhf(acc[nt][1] + b1) * a0 + x2.y * (1.0f - a0);
            *reinterpret_cast<float2*>(out + (size_t)n0g * C_DIM + col) = h;
        }
        if (v1) {
            const float2 x2 = *reinterpret_cast<const float2*>(X + (size_t)n1g * C_DIM + col);
            float2 h;
            h.x = tanhf(acc[nt][2] + b0) * a1 + x2.x * (1.0f - a1);
            h.y = tanhf(acc[nt][3] + b1) * a1 + x2.y * (1.0f - a1);
            *reinterpret_cast<float2*>(out + (size_t)n1g * C_DIM + col) = h;
        }
    }
}

// ---------------------------------------------------------------------------
// Launch
// ---------------------------------------------------------------------------
extern "C" void kernel_launch(void* const* d_in, const int* in_sizes, int n_in,
                              void* d_out, int out_size) {
    const float* X     = (const float*)d_in[0];
    const int*   ei    = (const int*)d_in[1];     // int32
    const int*   et    = (const int*)d_in[2];     // int32
    const float* relW  = (const float*)d_in[3];
    const float* rootW = (const float*)d_in[4];
    const float* bias  = (const float*)d_in[5];
    const float* attW  = (const float*)d_in[6];
    const float* attB  = (const float*)d_in[7];
    float*       out   = (float*)d_out;
    (void)in_sizes; (void)n_in; (void)out_size;

    cudaFuncSetAttribute(gemm_gate,
                         cudaFuncAttributeMaxDynamicSharedMemorySize, SMEM_BYTES);

    zero_counts_kernel<<<(NBUCKETS + 255) / 256, 256>>>();
    hist_kernel<<<(N_EDGES + 255) / 256, 256>>>(ei, et);
    wconv_kernel<<<(5 * C_DIM * C_DIM + 255) / 256, 256>>>(relW, rootW);
    xconv_kernel<<<(N_NODES * C_DIM / 4 + 255) / 256, 256>>>(X);
    scan_blocks_kernel<<<NSCANBLK, SCAN_BS>>>();
    scan_top_kernel<<<1, 256>>>();
    scan_add_kernel<<<(NBUCKETS + 255) / 256, 256>>>();
    bucket_kernel<<<(N_EDGES + 255) / 256, 256>>>(ei, et);
    agg_kernel<<<(NBUCKETS * 32 + 255) / 256, 256>>>();
    gemm_gate<<<(N_NODES + MB - 1) / MB, 512, SMEM_BYTES>>>(X, bias, attW, attB, out);
}

// round 11
// speedup vs baseline: 3.5262x; 1.0890x over previous
#include <cuda_runtime.h>
#include <cuda_fp16.h>
#include <cstdint>
#include <cstddef>

#define N_NODES   50000
#define N_EDGES   800000
#define C_DIM     256
#define R_REL     4
#define NBUCKETS  (R_REL * N_NODES)
#define SCAN_BS   1024
#define NSCANBLK  ((NBUCKETS + SCAN_BS - 1) / SCAN_BS)

// -------------------- scratch --------------------
__device__ int g_deg[NBUCKETS];
__device__ int g_off[NBUCKETS];     // after bucket_kernel: off_final = off + deg
__device__ int g_eidx[N_EDGES];
__device__ int g_bsum[SCAN_BS];
__device__ int g_bsumx[SCAN_BS];
__device__ float g_px[N_NODES];     // X[n] . attW[C:2C]
// fp16 weights [5][256][256] in [k][n] layout (root, rel0..3)
__device__ __half g_W[5 * C_DIM * C_DIM];
// fp16 A operand [5][N][256]: m=0 -> X(fp16), m=1..4 -> per-relation means
__device__ __half g_A[(size_t)5 * N_NODES * C_DIM];

__device__ __forceinline__ bool edge_ok(int s, int d, int r) {
    return ((unsigned)s < (unsigned)N_NODES) &&
           ((unsigned)d < (unsigned)N_NODES) &&
           ((unsigned)r < (unsigned)R_REL);
}

// ---------------------------------------------------------------------------
// CSR build (edges are INT32)
// ---------------------------------------------------------------------------
__global__ void zero_counts_kernel() {
    int i = blockIdx.x * blockDim.x + threadIdx.x;
    if (i < NBUCKETS) g_deg[i] = 0;
}

__global__ void hist_kernel(const int* __restrict__ edge_index,
                            const int* __restrict__ edge_type) {
    int e = blockIdx.x * blockDim.x + threadIdx.x;
    if (e >= N_EDGES) return;
    int s = edge_index[e];
    int d = edge_index[N_EDGES + e];
    int r = edge_type[e];
    if (!edge_ok(s, d, r)) return;
    atomicAdd(&g_deg[r * N_NODES + d], 1);
}

__global__ void scan_blocks_kernel() {
    __shared__ int sh[SCAN_BS];
    const int tid = threadIdx.x;
    const int gid = blockIdx.x * SCAN_BS + tid;
    int v = (gid < NBUCKETS) ? g_deg[gid] : 0;
    sh[tid] = v;
    __syncthreads();
    for (int o = 1; o < SCAN_BS; o <<= 1) {
        int t = (tid >= o) ? sh[tid - o] : 0;
        __syncthreads();
        sh[tid] += t;
        __syncthreads();
    }
    int incl = sh[tid];
    if (gid < NBUCKETS) g_off[gid] = incl - v;
    if (tid == SCAN_BS - 1) g_bsum[blockIdx.x] = incl;
}

__global__ void scan_top_kernel() {
    __shared__ int sh[256];
    const int tid = threadIdx.x;
    int v = (tid < NSCANBLK) ? g_bsum[tid] : 0;
    sh[tid] = v;
    __syncthreads();
    for (int o = 1; o < 256; o <<= 1) {
        int t = (tid >= o) ? sh[tid - o] : 0;
        __syncthreads();
        sh[tid] += t;
        __syncthreads();
    }
    g_bsumx[tid] = sh[tid] - v;
}

__global__ void scan_add_kernel() {
    int i = blockIdx.x * blockDim.x + threadIdx.x;
    if (i < NBUCKETS) g_off[i] += g_bsumx[i >> 10];
}

// bucket: post-increment g_off itself (no cursor array)
__global__ void bucket_kernel(const int* __restrict__ edge_index,
                              const int* __restrict__ edge_type) {
    int e = blockIdx.x * blockDim.x + threadIdx.x;
    if (e >= N_EDGES) return;
    int s = edge_index[e];
    int d = edge_index[N_EDGES + e];
    int r = edge_type[e];
    if (!edge_ok(s, d, r)) return;
    int b = r * N_NODES + d;
    int pos = atomicAdd(&g_off[b], 1);
    if ((unsigned)pos < (unsigned)N_EDGES)
        g_eidx[pos] = s;
}

// ---------------------------------------------------------------------------
// Fused conversion: W -> fp16 [m][k][n]; X -> g_A slot 0
// ---------------------------------------------------------------------------
#define W_G4 (5 * C_DIM * C_DIM / 4)          // 81920 float4-granules of W
#define X_G4 (N_NODES * C_DIM / 4)            // 3,200,000 granules of X
__global__ void conv_kernel(const float* __restrict__ relW,
                            const float* __restrict__ rootW,
                            const float* __restrict__ X) {
    int gid = blockIdx.x * blockDim.x + threadIdx.x;
    if (gid < W_G4) {
        const int i = gid * 4;        // element index into [5][64k]
        const int m = i >> 16;
        const int o = i & 65535;
        const float4 v = (m == 0)
            ? *reinterpret_cast<const float4*>(rootW + o)
            : *reinterpret_cast<const float4*>(relW + (size_t)(m - 1) * 65536 + o);
        __half h[4];
        h[0] = __float2half(v.x); h[1] = __float2half(v.y);
        h[2] = __float2half(v.z); h[3] = __float2half(v.w);
        *reinterpret_cast<uint2*>(g_W + i) = *reinterpret_cast<uint2*>(h);
    } else if (gid < W_G4 + X_G4) {
        const size_t i = (size_t)(gid - W_G4);
        const float4 v = reinterpret_cast<const float4*>(X)[i];
        __half h[4];
        h[0] = __float2half(v.x); h[1] = __float2half(v.y);
        h[2] = __float2half(v.z); h[3] = __float2half(v.w);
        *reinterpret_cast<uint2*>(g_A + 4 * i) = *reinterpret_cast<uint2*>(h);
    }
}

// px[n] = X16[n] . attW[C:2C]   (one warp per node, fp16 rows from g_A)
__global__ void px_kernel(const float* __restrict__ attW) {
    const int n    = (blockIdx.x * blockDim.x + threadIdx.x) >> 5;
    const int lane = threadIdx.x & 31;
    if (n >= N_NODES) return;
    const uint4 raw = *reinterpret_cast<const uint4*>(g_A + (size_t)n * C_DIM + lane * 8);
    const __half2* hp = reinterpret_cast<const __half2*>(&raw);
    float s = 0.f;
    #pragma unroll
    for (int q = 0; q < 4; ++q) {
        const float2 f = __half22float2(hp[q]);
        s += f.x * attW[C_DIM + lane * 8 + 2 * q]
           + f.y * attW[C_DIM + lane * 8 + 2 * q + 1];
    }
    #pragma unroll
    for (int o = 16; o; o >>= 1) s += __shfl_xor_sync(0xffffffffu, s, o);
    if (lane == 0) g_px[n] = s;
}

// Gather-mean per bucket over fp16 X -> g_A[1+r]
__global__ void agg_kernel() {
    const int wid  = (blockIdx.x * blockDim.x + threadIdx.x) >> 5;
    const int lane = threadIdx.x & 31;
    if (wid >= NBUCKETS) return;

    const int deg   = g_deg[wid];
    const int start = g_off[wid] - deg;    // off was post-incremented by bucket

    float s[8] = {0.f, 0.f, 0.f, 0.f, 0.f, 0.f, 0.f, 0.f};
    for (int e = 0; e < deg; ++e) {
        const int src = g_eidx[start + e];
        const uint4 raw = *reinterpret_cast<const uint4*>(
            g_A + (size_t)src * C_DIM + lane * 8);
        const __half2* hp = reinterpret_cast<const __half2*>(&raw);
        #pragma unroll
        for (int q = 0; q < 4; ++q) {
            const float2 f = __half22float2(hp[q]);
            s[2 * q]     += f.x;
            s[2 * q + 1] += f.y;
        }
    }
    const float inv = (deg > 0) ? (1.0f / (float)deg) : 0.0f;

    __half h[8];
    #pragma unroll
    for (int q = 0; q < 8; ++q) h[q] = __float2half(s[q] * inv);

    const size_t o = ((size_t)N_NODES * C_DIM) + (size_t)wid * C_DIM + lane * 8;
    *reinterpret_cast<uint4*>(g_A + o) = *reinterpret_cast<uint4*>(h);
}

// ---------------------------------------------------------------------------
// Dense GEMM (K=1280 concat, single-pass fp16) + gate epilogue.
// Tile M=128 x N=256, 512 threads = 16 warps (8m x 2n). 3-stage, KCH=64.
// ---------------------------------------------------------------------------
#define MB      128
#define KCH     64
#define NCHUNK  20
#define SAW     72      // A smem row stride (half): 144B, conflict-free rotation
#define SWW     264     // W smem row stride (half)
#define A_STAGE (MB * SAW)              // 9216 half
#define W_STAGE (KCH * SWW)             // 16896 half
#define STAGE_H (A_STAGE + W_STAGE)     // 26112 half
#define SMEM_BYTES (3 * STAGE_H * 2)    // 156,672 B

__device__ __forceinline__ void cp16(void* dst_smem, const void* src) {
    unsigned int d = (unsigned int)__cvta_generic_to_shared(dst_smem);
    asm volatile("cp.async.cg.shared.global [%0], [%1], 16;" :: "r"(d), "l"(src));
}
__device__ __forceinline__ void ldsm4(const void* p, unsigned& r0, unsigned& r1,
                                      unsigned& r2, unsigned& r3) {
    unsigned a = (unsigned)__cvta_generic_to_shared(p);
    asm volatile("ldmatrix.sync.aligned.m8n8.x4.shared.b16 {%0,%1,%2,%3}, [%4];"
                 : "=r"(r0), "=r"(r1), "=r"(r2), "=r"(r3) : "r"(a));
}
__device__ __forceinline__ void ldsm4t(const void* p, unsigned& r0, unsigned& r1,
                                       unsigned& r2, unsigned& r3) {
    unsigned a = (unsigned)__cvta_generic_to_shared(p);
    asm volatile("ldmatrix.sync.aligned.m8n8.x4.trans.shared.b16 {%0,%1,%2,%3}, [%4];"
                 : "=r"(r0), "=r"(r1), "=r"(r2), "=r"(r3) : "r"(a));
}
__device__ __forceinline__ void mma16816(float* c, unsigned a0, unsigned a1,
                                         unsigned a2, unsigned a3,
                                         unsigned b0, unsigned b1) {
    asm volatile(
        "mma.sync.aligned.m16n8k16.row.col.f32.f16.f16.f32 "
        "{%0,%1,%2,%3}, {%4,%5,%6,%7}, {%8,%9}, {%0,%1,%2,%3};"
        : "+f"(c[0]), "+f"(c[1]), "+f"(c[2]), "+f"(c[3])
        : "r"(a0), "r"(a1), "r"(a2), "r"(a3), "r"(b0), "r"(b1));
}

__global__ void __launch_bounds__(512, 1) gemm_gate(
    const float* __restrict__ X,
    const float* __restrict__ bias,
    const float* __restrict__ attW,
    const float* __restrict__ attB,
    float* __restrict__ out)
{
    extern __shared__ char smem_raw[];
    __half* sm = (__half*)smem_raw;
    float* pa = (float*)smem_raw;       // epilogue overlay

    const int t    = threadIdx.x;
    const int lane = t & 31;
    const int warp = t >> 5;
    const int wm   = warp & 7;      // 8 m-warps x 16 rows
    const int wn   = warp >> 3;     // 2 n-warps x 128 cols
    const int node0 = blockIdx.x * MB;

    float acc[16][4];
    #pragma unroll
    for (int i = 0; i < 16; ++i)
        #pragma unroll
        for (int j = 0; j < 4; ++j) acc[i][j] = 0.f;

    const int a_node = min(node0 + (t >> 2) , N_NODES - 1);   // rows via t>>2

    auto load_chunk = [&](int c, int stage) {
        const int m  = c >> 2;
        const int k0 = (c & 3) * KCH;
        __half* st = sm + stage * STAGE_H;
        // A: 128 rows x 64 halves = 1024 granules -> 2 per thread
        #pragma unroll
        for (int i = 0; i < 2; ++i) {
            const int p = t + 512 * i;          // 0..1023
            const int row = p >> 3, seg = p & 7;
            const int node = min(node0 + row, N_NODES - 1);
            const size_t g = ((size_t)m * N_NODES + node) * C_DIM + k0 + seg * 8;
            cp16(st + row * SAW + seg * 8, g_A + g);
        }
        // W: 64 rows x 256 halves = 2048 granules -> 4 per thread
        #pragma unroll
        for (int i = 0; i < 4; ++i) {
            const int p = t + 512 * i;          // 0..2047
            const int row = p >> 5, seg = p & 31;
            const size_t g = ((size_t)m * C_DIM + k0 + row) * C_DIM + seg * 8;
            cp16(st + A_STAGE + row * SWW + seg * 8, g_W + g);
        }
        asm volatile("cp.async.commit_group;");
    };
    (void)a_node;

    load_chunk(0, 0);
    load_chunk(1, 1);

    for (int c = 0; c < NCHUNK; ++c) {
        if (c + 1 < NCHUNK) asm volatile("cp.async.wait_group 1;");
        else                asm volatile("cp.async.wait_group 0;");
        __syncthreads();   // stage c visible; stage (c-1)%3 consumers done

        if (c + 2 < NCHUNK) load_chunk(c + 2, (c + 2) % 3);

        const __half* st = sm + (c % 3) * STAGE_H;
        const __half* Wb = st + A_STAGE;

        #pragma unroll
        for (int s = 0; s < 4; ++s) {
            const __half* ap =
                st + (wm * 16 + (lane & 15)) * SAW + s * 16 + (lane >> 4) * 8;
            unsigned a0, a1, a2, a3;
            ldsm4(ap, a0, a1, a2, a3);

            const int krow = s * 16 + (lane & 15);
            #pragma unroll
            for (int nt2 = 0; nt2 < 8; ++nt2) {
                const int ncol = wn * 128 + nt2 * 16 + (lane >> 4) * 8;
                unsigned b0, b1, b2, b3;
                ldsm4t(Wb + krow * SWW + ncol, b0, b1, b2, b3);
                mma16816(acc[2 * nt2],     a0, a1, a2, a3, b0, b1);
                mma16816(acc[2 * nt2 + 1], a0, a1, a2, a3, b2, b3);
            }
        }
    }
    __syncthreads();   // all computes done before smem overlay

    // ---------------- epilogue (register-resident; px precomputed) ----------
    const int r0   = lane >> 2;
    const int cq   = 2 * (lane & 3);
    const int row0 = wm * 16 + r0;
    const int n0g  = node0 + row0;
    const int n1g  = n0g + 8;
    const bool v0  = n0g < N_NODES;
    const bool v1  = n1g < N_NODES;

    float pz0 = 0.f, pz1 = 0.f;
    #pragma unroll
    for (int nt = 0; nt < 16; ++nt) {
        const int col = wn * 128 + (nt >> 1) * 16 + (nt & 1) * 8 + cq;
        const float b0 = bias[col], b1 = bias[col + 1];
        const float wu0 = attW[col], wu1 = attW[col + 1];
        pz0 += (acc[nt][0] + b0) * wu0 + (acc[nt][1] + b1) * wu1;
        pz1 += (acc[nt][2] + b0) * wu0 + (acc[nt][3] + b1) * wu1;
    }
    pz0 += __shfl_xor_sync(0xffffffffu, pz0, 1);
    pz0 += __shfl_xor_sync(0xffffffffu, pz0, 2);
    pz1 += __shfl_xor_sync(0xffffffffu, pz1, 1);
    pz1 += __shfl_xor_sync(0xffffffffu, pz1, 2);

    if ((lane & 3) == 0) {
        pa[row0 * 2 + wn]       = pz0;
        pa[(row0 + 8) * 2 + wn] = pz1;
    }
    __syncthreads();
    float* a_s = pa + 2 * MB;
    if (t < MB) {
        const int node = node0 + t;
        const float px = (node < N_NODES) ? g_px[node] : 0.f;
        const float z = pa[t * 2] + pa[t * 2 + 1] + px + attB[0];
        a_s[t] = 1.0f / (1.0f + expf(-z));
    }
    __syncthreads();

    const float a0 = a_s[row0], a1 = a_s[row0 + 8];
    #pragma unroll
    for (int nt = 0; nt < 16; ++nt) {
        const int col = wn * 128 + (nt >> 1) * 16 + (nt & 1) * 8 + cq;
        const float b0 = bias[col], b1 = bias[col + 1];
        if (v0) {
            const float2 x2 = *reinterpret_cast<const float2*>(X + (size_t)n0g * C_DIM + col);
            float2 h;
            h.x = tanhf(acc[nt][0] + b0) * a0 + x2.x * (1.0f - a0);
            h.y = tanhf(acc[nt][1] + b1) * a0 + x2.y * (1.0f - a0);
            *reinterpret_cast<float2*>(out + (size_t)n0g * C_DIM + col) = h;
        }
        if (v1) {
            const float2 x2 = *reinterpret_cast<const float2*>(X + (size_t)n1g * C_DIM + col);
            float2 h;
            h.x = tanhf(acc[nt][2] + b0) * a1 + x2.x * (1.0f - a1);
            h.y = tanhf(acc[nt][3] + b1) * a1 + x2.y * (1.0f - a1);
            *reinterpret_cast<float2*>(out + (size_t)n1g * C_DIM + col) = h;
        }
    }
}

// ---------------------------------------------------------------------------
// Launch
// ---------------------------------------------------------------------------
extern "C" void kernel_launch(void* const* d_in, const int* in_sizes, int n_in,
                              void* d_out, int out_size) {
    const float* X     = (const float*)d_in[0];
    const int*   ei    = (const int*)d_in[1];     // int32
    const int*   et    = (const int*)d_in[2];     // int32
    const float* relW  = (const float*)d_in[3];
    const float* rootW = (const float*)d_in[4];
    const float* bias  = (const float*)d_in[5];
    const float* attW  = (const float*)d_in[6];
    const float* attB  = (const float*)d_in[7];
    float*       out   = (float*)d_out;
    (void)in_sizes; (void)n_in; (void)out_size;

    cudaFuncSetAttribute(gemm_gate,
                         cudaFuncAttributeMaxDynamicSharedMemorySize, SMEM_BYTES);

    zero_counts_kernel<<<(NBUCKETS + 255) / 256, 256>>>();
    hist_kernel<<<(N_EDGES + 255) / 256, 256>>>(ei, et);
    conv_kernel<<<(W_G4 + X_G4 + 255) / 256, 256>>>(relW, rootW, X);
    px_kernel<<<(N_NODES * 32 + 255) / 256, 256>>>(attW);
    scan_blocks_kernel<<<NSCANBLK, SCAN_BS>>>();
    scan_top_kernel<<<1, 256>>>();
    scan_add_kernel<<<(NBUCKETS + 255) / 256, 256>>>();
    bucket_kernel<<<(N_EDGES + 255) / 256, 256>>>(ei, et);
    agg_kernel<<<(NBUCKETS * 32 + 255) / 256, 256>>>();
    gemm_gate<<<(N_NODES + MB - 1) / MB, 512, SMEM_BYTES>>>(X, bias, attW, attB, out);
}